// round 3
// baseline (speedup 1.0000x reference)
#include <cuda_runtime.h>
#include <cuda_bf16.h>

#define B_   8
#define T0_  16384
#define T1_  16383
#define T2_  16382
#define TFIN 15360

// -------- scratch (device globals; no allocation allowed) --------
__device__ float g_y1 [(size_t)B_ * T1_ * 256]; // causal out
__device__ float g_zgf[(size_t)B_ * T2_ * 48];  // gated0 pre-activation (g|f)
__device__ float g_hA [(size_t)B_ * T2_ * 24];  // ping
__device__ float g_hB [(size_t)B_ * T2_ * 24];  // pong
__device__ float g_a0 [(size_t)B_ * TFIN * 128];
__device__ float g_a1 [(size_t)B_ * TFIN * 256];
__device__ float g_wp [512 * 48 + 48];          // packed gated0 weights+bias

// ============================================================================
// GEMM 128x128x8, 8x8 register tile, batched via blockIdx.z.
// A rows may overlap (lda < K) -- used to express K=2 conv as GEMM.
// Requires: K % 8 == 0, N % 128 == 0, A 16B-aligned rows (lda % 4 == 0).
// ============================================================================
__global__ __launch_bounds__(256) void gemm128(
    const float* __restrict__ A, const float* __restrict__ Bw,
    const float* __restrict__ bias, float* __restrict__ C,
    int Mrows, int N, int K, int lda, long sA, long sC, int act)
{
    __shared__ float As[8][128];
    __shared__ float Bs[8][128];
    const int m0 = blockIdx.x * 128;
    const int n0 = blockIdx.y * 128;
    const float* Ab = A + (long)blockIdx.z * sA;
    float* Cb = C + (long)blockIdx.z * sC;
    const int tid  = threadIdx.x;
    const int arow = tid >> 1;
    const int akq  = (tid & 1) * 4;
    const int bk   = tid >> 5;
    const int bn   = (tid & 31) * 4;
    const int tr   = (tid >> 4) * 8;
    const int tc   = (tid & 15) * 8;

    float acc[8][8];
#pragma unroll
    for (int i = 0; i < 8; i++)
#pragma unroll
        for (int j = 0; j < 8; j++) acc[i][j] = 0.f;

    const int gm_l = m0 + arow;
    for (int k0 = 0; k0 < K; k0 += 8) {
        float4 av = make_float4(0.f, 0.f, 0.f, 0.f);
        if (gm_l < Mrows)
            av = *reinterpret_cast<const float4*>(&Ab[(long)gm_l * lda + k0 + akq]);
        As[akq + 0][arow] = av.x;
        As[akq + 1][arow] = av.y;
        As[akq + 2][arow] = av.z;
        As[akq + 3][arow] = av.w;
        float4 bv = *reinterpret_cast<const float4*>(&Bw[(long)(k0 + bk) * N + n0 + bn]);
        *reinterpret_cast<float4*>(&Bs[bk][bn]) = bv;
        __syncthreads();
#pragma unroll
        for (int kk = 0; kk < 8; kk++) {
            float4 a0v = *reinterpret_cast<float4*>(&As[kk][tr]);
            float4 a1v = *reinterpret_cast<float4*>(&As[kk][tr + 4]);
            float4 b0v = *reinterpret_cast<float4*>(&Bs[kk][tc]);
            float4 b1v = *reinterpret_cast<float4*>(&Bs[kk][tc + 4]);
            float af[8] = {a0v.x, a0v.y, a0v.z, a0v.w, a1v.x, a1v.y, a1v.z, a1v.w};
            float bf[8] = {b0v.x, b0v.y, b0v.z, b0v.w, b1v.x, b1v.y, b1v.z, b1v.w};
#pragma unroll
            for (int i = 0; i < 8; i++)
#pragma unroll
                for (int j = 0; j < 8; j++) acc[i][j] += af[i] * bf[j];
        }
        __syncthreads();
    }

#pragma unroll
    for (int i = 0; i < 8; i++) {
        int gm = m0 + tr + i;
        if (gm >= Mrows) continue;
        long base = (long)gm * N + n0 + tc;
#pragma unroll
        for (int j = 0; j < 8; j++) {
            float v = acc[i][j] + bias[n0 + tc + j];
            if (act) v = fmaxf(v, 0.f);
            Cb[base + j] = v;
        }
    }
}

// ============================================================================
// GEMM 64x64x8, 4x4 tile, fully guarded N (used for gated0: N=48).
// ============================================================================
__global__ __launch_bounds__(256) void gemm64(
    const float* __restrict__ A, const float* __restrict__ Bw,
    const float* __restrict__ bias, float* __restrict__ C,
    int Mrows, int N, int K, int lda, long sA, long sC, int act)
{
    __shared__ float As[8][64];
    __shared__ float Bs[8][64];
    const int m0 = blockIdx.x * 64;
    const int n0 = blockIdx.y * 64;
    const float* Ab = A + (long)blockIdx.z * sA;
    float* Cb = C + (long)blockIdx.z * sC;
    const int tid  = threadIdx.x;
    const int arow = tid >> 2;
    const int ak   = tid & 3;
    const int bkr  = tid >> 5;
    const int bnn  = tid & 31;
    const int tr   = (tid >> 4) * 4;
    const int tc   = (tid & 15) * 4;

    float acc[4][4];
#pragma unroll
    for (int i = 0; i < 4; i++)
#pragma unroll
        for (int j = 0; j < 4; j++) acc[i][j] = 0.f;

    const int gm_l = m0 + arow;
    for (int k0 = 0; k0 < K; k0 += 8) {
        float a0v = 0.f, a1v = 0.f;
        if (gm_l < Mrows) {
            long off = (long)gm_l * lda + k0 + ak;
            a0v = Ab[off];
            a1v = Ab[off + 4];
        }
        As[ak][arow]     = a0v;
        As[ak + 4][arow] = a1v;
        int gn = n0 + bnn;
        Bs[bkr][bnn]      = (gn < N)      ? Bw[(long)(k0 + bkr) * N + gn]      : 0.f;
        Bs[bkr][bnn + 32] = (gn + 32 < N) ? Bw[(long)(k0 + bkr) * N + gn + 32] : 0.f;
        __syncthreads();
#pragma unroll
        for (int kk = 0; kk < 8; kk++) {
            float af[4], bf[4];
#pragma unroll
            for (int i = 0; i < 4; i++) af[i] = As[kk][tr + i];
#pragma unroll
            for (int j = 0; j < 4; j++) bf[j] = Bs[kk][tc + j];
#pragma unroll
            for (int i = 0; i < 4; i++)
#pragma unroll
                for (int j = 0; j < 4; j++) acc[i][j] += af[i] * bf[j];
        }
        __syncthreads();
    }

#pragma unroll
    for (int i = 0; i < 4; i++) {
        int gm = m0 + tr + i;
        if (gm >= Mrows) continue;
#pragma unroll
        for (int j = 0; j < 4; j++) {
            int gn = n0 + tc + j;
            if (gn >= N) continue;
            float v = acc[i][j] + bias[gn];
            if (act) v = fmaxf(v, 0.f);
            Cb[(long)gm * N + gn] = v;
        }
    }
}

// ============================================================================
// Pack gated0 weights: wp[k][n] = (n<24) ? gW0[k][n] : fW0[k][n-24]; bias at end.
// ============================================================================
__global__ void pack_gf(const float* __restrict__ gW, const float* __restrict__ gb,
                        const float* __restrict__ fW, const float* __restrict__ fb,
                        float* __restrict__ wp)
{
    int idx = blockIdx.x * 256 + threadIdx.x;
    if (idx < 512 * 48) {
        int k = idx / 48, n = idx % 48;
        wp[idx] = (n < 24) ? gW[k * 24 + n] : fW[k * 24 + n - 24];
    } else if (idx < 512 * 48 + 48) {
        int n = idx - 512 * 48;
        wp[idx] = (n < 24) ? gb[n] : fb[n - 24];
    }
}

__device__ __forceinline__ float sigmoidf_(float x) { return 1.f / (1.f + __expf(-x)); }

// ============================================================================
// gated0 elementwise + 1x1 scale: h = (sig(g)*tanh(f)) @ sW0 + sb0
// ============================================================================
__global__ __launch_bounds__(128) void gated0_ew(
    const float* __restrict__ zgf, const float* __restrict__ sW,
    const float* __restrict__ sB, float* __restrict__ h)
{
    __shared__ float zs[128][49];
    __shared__ float sw[24][24];
    __shared__ float sb_s[24];
    const long M = (long)B_ * T2_;
    const long t0 = (long)blockIdx.x * 128;
    const int tid = threadIdx.x;
    for (int i = tid; i < 576; i += 128) sw[i / 24][i % 24] = sW[i];
    if (tid < 24) sb_s[tid] = sB[tid];
    for (int i = tid; i < 128 * 48; i += 128) {
        int r = i / 48, c = i % 48;
        long t = t0 + r;
        zs[r][c] = (t < M) ? zgf[t * 48 + c] : 0.f;
    }
    __syncthreads();
    long t = t0 + tid;
    if (t >= M) return;
    float z[24];
#pragma unroll
    for (int c = 0; c < 24; c++)
        z[c] = sigmoidf_(zs[tid][c]) * tanhf(zs[tid][24 + c]);
    float* ob = h + t * 24;
#pragma unroll
    for (int o = 0; o < 24; o++) {
        float a = sb_s[o];
#pragma unroll
        for (int c = 0; c < 24; c++) a += z[c] * sw[c][o];
        ob[o] = a;
    }
}

// ============================================================================
// Fused dilated gated layer (24 ch): g/f conv (K=2, dil d) + sig*tanh + 1x1.
// ============================================================================
__global__ __launch_bounds__(128) void dilated_gated(
    const float* __restrict__ hin, float* __restrict__ hout,
    const float* __restrict__ gateW, const float* __restrict__ gateB,
    const float* __restrict__ filtW, const float* __restrict__ filtB,
    const float* __restrict__ scaleW, const float* __restrict__ scaleB,
    int layer, int Tin, int Tout, int d)
{
    __shared__ float  xs0[128][25];
    __shared__ float  xs1[128][25];
    __shared__ float4 wpk[24][24];  // {gw_k0, gw_k1, fw_k0, fw_k1}
    __shared__ float  sw[24][24];
    __shared__ float  gb_s[24], fb_s[24], sb_s[24];
    const int tid = threadIdx.x;
    const int b   = blockIdx.y;
    const int t0  = blockIdx.x * 128;
    const int wbase = layer * 1152;
    for (int i = tid; i < 576; i += 128) {
        int c = i / 24, o = i % 24;
        wpk[c][o] = make_float4(gateW[wbase + i], gateW[wbase + 576 + i],
                                filtW[wbase + i], filtW[wbase + 576 + i]);
        sw[c][o] = scaleW[layer * 576 + i];
    }
    if (tid < 24) {
        gb_s[tid] = gateB[layer * 24 + tid];
        fb_s[tid] = filtB[layer * 24 + tid];
        sb_s[tid] = scaleB[layer * 24 + tid];
    }
    const float* hb = hin + (long)b * Tin * 24;
    for (int i = tid; i < 128 * 24; i += 128) {
        int r = i / 24, c = i % 24;
        int ta = t0 + r, tb = t0 + d + r;
        xs0[r][c] = (ta < Tin) ? hb[(long)ta * 24 + c] : 0.f;
        xs1[r][c] = (tb < Tin) ? hb[(long)tb * 24 + c] : 0.f;
    }
    __syncthreads();
    int t = t0 + tid;
    if (t >= Tout) return;
    float gA[24], fA[24];
#pragma unroll
    for (int o = 0; o < 24; o++) { gA[o] = gb_s[o]; fA[o] = fb_s[o]; }
#pragma unroll
    for (int c = 0; c < 24; c++) {
        float x0 = xs0[tid][c], x1 = xs1[tid][c];
#pragma unroll
        for (int o = 0; o < 24; o++) {
            float4 w = wpk[c][o];
            gA[o] += x0 * w.x + x1 * w.y;
            fA[o] += x0 * w.z + x1 * w.w;
        }
    }
    float z[24];
#pragma unroll
    for (int o = 0; o < 24; o++) z[o] = sigmoidf_(gA[o]) * tanhf(fA[o]);
    float* ob = hout + ((long)b * Tout + t) * 24;
#pragma unroll
    for (int o2 = 0; o2 < 24; o2++) {
        float a = sb_s[o2];
#pragma unroll
        for (int c = 0; c < 24; c++) a += z[c] * sw[c][o2];
        ob[o2] = a;
    }
}

// ============================================================================
// Final residual add + res conv (24->128) + relu:
// a0[b,t,:] = relu( (prev8[b,t+256,:] + out8[b,t,:]) @ resW[8] + resB[8] )
// ============================================================================
__global__ __launch_bounds__(128) void resconv_relu(
    const float* __restrict__ prev8, const float* __restrict__ out8,
    const float* __restrict__ resW, const float* __restrict__ resB,
    float* __restrict__ a0out)
{
    __shared__ float ss[32][25];
    __shared__ float Ws[24][128];
    __shared__ float bs[128];
    const int tid = threadIdx.x;
    const int b   = blockIdx.y;
    const int t0  = blockIdx.x * 32;
    for (int i = tid; i < 24 * 128; i += 128) Ws[i / 128][i % 128] = resW[8 * 24 * 128 + i];
    bs[tid] = resB[8 * 128 + tid];
    const float* pb = prev8 + ((long)b * 15872 + 256) * 24;
    const float* ob = out8  + (long)b * TFIN * 24;
    for (int i = tid; i < 32 * 24; i += 128) {
        int r = i / 24, c = i % 24;
        long t = t0 + r;
        ss[r][c] = pb[t * 24 + c] + ob[t * 24 + c];
    }
    __syncthreads();
    float* outb = a0out + ((long)b * TFIN + t0) * 128;
#pragma unroll 4
    for (int r = 0; r < 32; r++) {
        float a = bs[tid];
#pragma unroll
        for (int c = 0; c < 24; c++) a += ss[r][c] * Ws[c][tid];
        outb[(long)r * 128 + tid] = fmaxf(a, 0.f);
    }
}

// ============================================================================
// Softmax over last dim (256), warp per row, in place.
// ============================================================================
__global__ void softmax256(float* __restrict__ out, long rows)
{
    long warp = (((long)blockIdx.x * blockDim.x) + threadIdx.x) >> 5;
    int lane = threadIdx.x & 31;
    if (warp >= rows) return;
    float* row = out + warp * 256;
    float v[8];
    float mx = -1e30f;
#pragma unroll
    for (int j = 0; j < 8; j++) { v[j] = row[lane + 32 * j]; mx = fmaxf(mx, v[j]); }
#pragma unroll
    for (int s = 16; s > 0; s >>= 1) mx = fmaxf(mx, __shfl_xor_sync(0xffffffffu, mx, s));
    float sum = 0.f;
#pragma unroll
    for (int j = 0; j < 8; j++) { v[j] = __expf(v[j] - mx); sum += v[j]; }
#pragma unroll
    for (int s = 16; s > 0; s >>= 1) sum += __shfl_xor_sync(0xffffffffu, sum, s);
    float inv = 1.f / sum;
#pragma unroll
    for (int j = 0; j < 8; j++) row[lane + 32 * j] = v[j] * inv;
}

// ============================================================================
extern "C" void kernel_launch(void* const* d_in, const int* in_sizes, int n_in,
                              void* d_out, int out_size)
{
    const float* x        = (const float*)d_in[0];
    const float* causal_W = (const float*)d_in[1];
    const float* causal_b = (const float*)d_in[2];
    const float* gW0      = (const float*)d_in[3];
    const float* gb0      = (const float*)d_in[4];
    const float* fW0      = (const float*)d_in[5];
    const float* fb0      = (const float*)d_in[6];
    const float* sW0      = (const float*)d_in[7];
    const float* sb0      = (const float*)d_in[8];
    const float* gateW    = (const float*)d_in[9];
    const float* gateB    = (const float*)d_in[10];
    const float* filtW    = (const float*)d_in[11];
    const float* filtB    = (const float*)d_in[12];
    const float* scaleW   = (const float*)d_in[13];
    const float* scaleB   = (const float*)d_in[14];
    const float* resW     = (const float*)d_in[15];
    const float* resB     = (const float*)d_in[16];
    const float* f1W      = (const float*)d_in[17];
    const float* f1b      = (const float*)d_in[18];
    const float* f2W      = (const float*)d_in[19];
    const float* f2b      = (const float*)d_in[20];
    float* out = (float*)d_out;

    float *y1, *zgf, *hA, *hB, *a0, *a1, *wp;
    cudaGetSymbolAddress((void**)&y1,  g_y1);
    cudaGetSymbolAddress((void**)&zgf, g_zgf);
    cudaGetSymbolAddress((void**)&hA,  g_hA);
    cudaGetSymbolAddress((void**)&hB,  g_hB);
    cudaGetSymbolAddress((void**)&a0,  g_a0);
    cudaGetSymbolAddress((void**)&a1,  g_a1);
    cudaGetSymbolAddress((void**)&wp,  g_wp);

    // 1. pack gated0 weights (g|f) -> [512,48] + bias[48]
    pack_gf<<<97, 256>>>(gW0, gb0, fW0, fb0, wp);

    // 2. causal conv as GEMM: y1[b,t,:] = x[b,t..t+1,:] @ W  (K=512 overlap trick)
    {
        dim3 g(128, 2, B_);
        gemm128<<<g, 256>>>(x, causal_W, causal_b, y1,
                            T1_, 256, 512, 256,
                            (long)T0_ * 256, (long)T1_ * 256, 0);
    }

    // 3. gated0 g/f convs as one GEMM: zgf[b,t,0:48]
    {
        dim3 g(256, 1, B_);
        gemm64<<<g, 256>>>(y1, wp, wp + 512 * 48, zgf,
                           T2_, 48, 512, 256,
                           (long)T1_ * 256, (long)T2_ * 48, 0);
    }

    // 4. gated0 activation + 1x1 -> hA
    gated0_ew<<<1024, 128>>>(zgf, sW0, sb0, hA);

    // 5. nine dilated gated layers (ping-pong hA/hB)
    int Tin = T2_;
    float* hin  = hA;
    float* hnew = hB;
    for (int i = 0; i < 9; i++) {
        int d = 2 << i;
        int Tout = Tin - d;
        dim3 g((Tout + 127) / 128, B_);
        dilated_gated<<<g, 128>>>(hin, hnew, gateW, gateB, filtW, filtB,
                                  scaleW, scaleB, i, Tin, Tout, d);
        float* tmp = hin; hin = hnew; hnew = tmp;
        Tin = Tout;
    }
    // hin = layer-8 output (T=15360), hnew = layer-7 output (T=15872)

    // 6. residual add + res conv (only res_W[8] matters) + relu -> a0
    resconv_relu<<<dim3(480, B_), 128>>>(hnew, hin, resW, resB, a0);

    // 7. f1: [122880,128] @ [128,256] + relu
    gemm128<<<dim3(960, 2, 1), 256>>>(a0, f1W, f1b, a1,
                                      B_ * TFIN, 256, 128, 128, 0, 0, 1);

    // 8. f2: [122880,256] @ [256,256] -> logits in d_out
    gemm128<<<dim3(960, 2, 1), 256>>>(a1, f2W, f2b, out,
                                      B_ * TFIN, 256, 256, 256, 0, 0, 0);

    // 9. softmax in place
    softmax256<<<15360, 256>>>(out, (long)B_ * TFIN);
}

// round 4
// speedup vs baseline: 1.0896x; 1.0896x over previous
#include <cuda_runtime.h>
#include <cuda_bf16.h>

#define B_   8
#define T0_  16384
#define T1_  16383
#define T2_  16382
#define TFIN 15360

typedef unsigned long long ULL;

// -------- scratch (device globals; no allocation allowed) --------
__device__ float g_y1 [(size_t)B_ * T1_ * 256]; // causal out
__device__ float g_zgf[(size_t)B_ * T2_ * 48];  // gated0 pre-activation (g|f)
__device__ float g_hA [(size_t)B_ * T2_ * 24];  // ping
__device__ float g_hB [(size_t)B_ * T2_ * 24];  // pong
__device__ float g_a0 [(size_t)B_ * TFIN * 128];
__device__ float g_a1 [(size_t)B_ * TFIN * 256];
__device__ float g_wp [512 * 48 + 48];          // packed gated0 weights+bias

// -------- f32x2 packed-FMA helpers (sm_103a FFMA2 via PTX) --------
__device__ __forceinline__ ULL dup2(float x) {
    ULL r; asm("mov.b64 %0, {%1, %1};" : "=l"(r) : "f"(x)); return r;
}
__device__ __forceinline__ ULL pk2(float lo, float hi) {
    ULL r; asm("mov.b64 %0, {%1, %2};" : "=l"(r) : "f"(lo), "f"(hi)); return r;
}
__device__ __forceinline__ float2 unpk2(ULL v) {
    float2 f; asm("mov.b64 {%0, %1}, %2;" : "=f"(f.x), "=f"(f.y) : "l"(v)); return f;
}
__device__ __forceinline__ void ffma2(ULL& d, ULL a, ULL b) {
    asm("fma.rn.f32x2 %0, %1, %2, %0;" : "+l"(d) : "l"(a), "l"(b));
}

__device__ __forceinline__ float sigmoidf_(float x) { return 1.f / (1.f + __expf(-x)); }
__device__ __forceinline__ float tanhf_(float x) {
    float e = __expf(2.f * x);
    return 1.f - 2.f / (e + 1.f);
}

// ============================================================================
// GEMM 128x128x8, 8x8 register tile via f32x2 packed FMA, batched blockIdx.z.
// A rows may overlap (lda < K) -- used to express K=2 conv as GEMM.
// Requires: K % 8 == 0, N % 128 == 0, A rows 16B-aligned.
// ============================================================================
__global__ __launch_bounds__(256) void gemm128(
    const float* __restrict__ A, const float* __restrict__ Bw,
    const float* __restrict__ bias, float* __restrict__ C,
    int Mrows, int N, int K, int lda, long sA, long sC, int act)
{
    __shared__ float As[8][128];
    __shared__ float Bs[8][128];
    const int m0 = blockIdx.x * 128;
    const int n0 = blockIdx.y * 128;
    const float* Ab = A + (long)blockIdx.z * sA;
    float* Cb = C + (long)blockIdx.z * sC;
    const int tid  = threadIdx.x;
    const int arow = tid >> 1;
    const int akq  = (tid & 1) * 4;
    const int bk   = tid >> 5;
    const int bn   = (tid & 31) * 4;
    const int tr   = (tid >> 4) * 8;
    const int tc   = (tid & 15) * 8;

    ULL acc2[8][4];
#pragma unroll
    for (int i = 0; i < 8; i++)
#pragma unroll
        for (int j = 0; j < 4; j++) acc2[i][j] = 0ull;

    const int gm_l = m0 + arow;
    for (int k0 = 0; k0 < K; k0 += 8) {
        float4 av = make_float4(0.f, 0.f, 0.f, 0.f);
        if (gm_l < Mrows)
            av = *reinterpret_cast<const float4*>(&Ab[(long)gm_l * lda + k0 + akq]);
        As[akq + 0][arow] = av.x;
        As[akq + 1][arow] = av.y;
        As[akq + 2][arow] = av.z;
        As[akq + 3][arow] = av.w;
        float4 bv = *reinterpret_cast<const float4*>(&Bw[(long)(k0 + bk) * N + n0 + bn]);
        *reinterpret_cast<float4*>(&Bs[bk][bn]) = bv;
        __syncthreads();
#pragma unroll
        for (int kk = 0; kk < 8; kk++) {
            float4 a0v = *reinterpret_cast<float4*>(&As[kk][tr]);
            float4 a1v = *reinterpret_cast<float4*>(&As[kk][tr + 4]);
            ulonglong2 b0 = *reinterpret_cast<ulonglong2*>(&Bs[kk][tc]);
            ulonglong2 b1 = *reinterpret_cast<ulonglong2*>(&Bs[kk][tc + 4]);
            ULL bb[4] = {b0.x, b0.y, b1.x, b1.y};
            ULL ad[8] = {dup2(a0v.x), dup2(a0v.y), dup2(a0v.z), dup2(a0v.w),
                         dup2(a1v.x), dup2(a1v.y), dup2(a1v.z), dup2(a1v.w)};
#pragma unroll
            for (int i = 0; i < 8; i++)
#pragma unroll
                for (int j = 0; j < 4; j++) ffma2(acc2[i][j], ad[i], bb[j]);
        }
        __syncthreads();
    }

#pragma unroll
    for (int i = 0; i < 8; i++) {
        int gm = m0 + tr + i;
        if (gm >= Mrows) continue;
        long base = (long)gm * N + n0 + tc;
#pragma unroll
        for (int j = 0; j < 4; j++) {
            float2 v = unpk2(acc2[i][j]);
            v.x += bias[n0 + tc + 2 * j];
            v.y += bias[n0 + tc + 2 * j + 1];
            if (act) { v.x = fmaxf(v.x, 0.f); v.y = fmaxf(v.y, 0.f); }
            *reinterpret_cast<float2*>(&Cb[base + 2 * j]) = v;
        }
    }
}

// ============================================================================
// GEMM 64x64x8, 4x4 tile via f32x2, guarded N (used for gated0: N=48).
// ============================================================================
__global__ __launch_bounds__(256) void gemm64(
    const float* __restrict__ A, const float* __restrict__ Bw,
    const float* __restrict__ bias, float* __restrict__ C,
    int Mrows, int N, int K, int lda, long sA, long sC, int act)
{
    __shared__ float As[8][64];
    __shared__ float Bs[8][64];
    const int m0 = blockIdx.x * 64;
    const int n0 = blockIdx.y * 64;
    const float* Ab = A + (long)blockIdx.z * sA;
    float* Cb = C + (long)blockIdx.z * sC;
    const int tid  = threadIdx.x;
    const int arow = tid >> 2;
    const int ak   = tid & 3;
    const int bkr  = tid >> 5;
    const int bnn  = tid & 31;
    const int tr   = (tid >> 4) * 4;
    const int tc   = (tid & 15) * 4;

    ULL acc2[4][2];
#pragma unroll
    for (int i = 0; i < 4; i++) { acc2[i][0] = 0ull; acc2[i][1] = 0ull; }

    const int gm_l = m0 + arow;
    for (int k0 = 0; k0 < K; k0 += 8) {
        float a0v = 0.f, a1v = 0.f;
        if (gm_l < Mrows) {
            long off = (long)gm_l * lda + k0 + ak;
            a0v = Ab[off];
            a1v = Ab[off + 4];
        }
        As[ak][arow]     = a0v;
        As[ak + 4][arow] = a1v;
        int gn = n0 + bnn;
        Bs[bkr][bnn]      = (gn < N)      ? Bw[(long)(k0 + bkr) * N + gn]      : 0.f;
        Bs[bkr][bnn + 32] = (gn + 32 < N) ? Bw[(long)(k0 + bkr) * N + gn + 32] : 0.f;
        __syncthreads();
#pragma unroll
        for (int kk = 0; kk < 8; kk++) {
            ulonglong2 bv = *reinterpret_cast<ulonglong2*>(&Bs[kk][tc]);
            ULL bb[2] = {bv.x, bv.y};
            ULL ad[4] = {dup2(As[kk][tr + 0]), dup2(As[kk][tr + 1]),
                         dup2(As[kk][tr + 2]), dup2(As[kk][tr + 3])};
#pragma unroll
            for (int i = 0; i < 4; i++) {
                ffma2(acc2[i][0], ad[i], bb[0]);
                ffma2(acc2[i][1], ad[i], bb[1]);
            }
        }
        __syncthreads();
    }

#pragma unroll
    for (int i = 0; i < 4; i++) {
        int gm = m0 + tr + i;
        if (gm >= Mrows) continue;
#pragma unroll
        for (int j = 0; j < 2; j++) {
            float2 v = unpk2(acc2[i][j]);
            int gn = n0 + tc + 2 * j;
            if (gn < N) {
                float r = v.x + bias[gn];
                Cb[(long)gm * N + gn] = act ? fmaxf(r, 0.f) : r;
            }
            if (gn + 1 < N) {
                float r = v.y + bias[gn + 1];
                Cb[(long)gm * N + gn + 1] = act ? fmaxf(r, 0.f) : r;
            }
        }
    }
}

// ============================================================================
// Pack gated0 weights: wp[k][n] = (n<24) ? gW0[k][n] : fW0[k][n-24]; bias end.
// ============================================================================
__global__ void pack_gf(const float* __restrict__ gW, const float* __restrict__ gb,
                        const float* __restrict__ fW, const float* __restrict__ fb,
                        float* __restrict__ wp)
{
    int idx = blockIdx.x * 256 + threadIdx.x;
    if (idx < 512 * 48) {
        int k = idx / 48, n = idx % 48;
        wp[idx] = (n < 24) ? gW[k * 24 + n] : fW[k * 24 + n - 24];
    } else if (idx < 512 * 48 + 48) {
        int n = idx - 512 * 48;
        wp[idx] = (n < 24) ? gb[n] : fb[n - 24];
    }
}

// ============================================================================
// gated0 elementwise + 1x1 scale (f32x2): h = (sig(g)*tanh(f)) @ sW0 + sb0
// ============================================================================
__global__ __launch_bounds__(128) void gated0_ew(
    const float* __restrict__ zgf, const float* __restrict__ sW,
    const float* __restrict__ sB, float* __restrict__ h)
{
    __shared__ float zs[128][49];
    __shared__ ULL   sp[24][12];
    __shared__ ULL   sb2[12];
    const long M = (long)B_ * T2_;
    const long t0 = (long)blockIdx.x * 128;
    const int tid = threadIdx.x;
    for (int i = tid; i < 288; i += 128) {
        int c = i / 12, p = i % 12;
        sp[c][p] = pk2(sW[c * 24 + 2 * p], sW[c * 24 + 2 * p + 1]);
    }
    if (tid < 12) sb2[tid] = pk2(sB[2 * tid], sB[2 * tid + 1]);
    for (int i = tid; i < 128 * 48; i += 128) {
        int r = i / 48, c = i % 48;
        long t = t0 + r;
        zs[r][c] = (t < M) ? zgf[t * 48 + c] : 0.f;
    }
    __syncthreads();
    long t = t0 + tid;
    if (t >= M) return;
    float z[24];
#pragma unroll
    for (int c = 0; c < 24; c++)
        z[c] = sigmoidf_(zs[tid][c]) * tanhf_(zs[tid][24 + c]);
    ULL o2[12];
#pragma unroll
    for (int p = 0; p < 12; p++) o2[p] = sb2[p];
#pragma unroll
    for (int c = 0; c < 24; c++) {
        ULL zd = dup2(z[c]);
#pragma unroll
        for (int p = 0; p < 12; p++) ffma2(o2[p], zd, sp[c][p]);
    }
    ULL* ob = reinterpret_cast<ULL*>(h + t * 24);
#pragma unroll
    for (int p = 0; p < 12; p++) ob[p] = o2[p];
}

// ============================================================================
// Fused dilated gated layer (24 ch, f32x2): K=2 dilated g/f conv + sig*tanh + 1x1.
// ============================================================================
__global__ __launch_bounds__(128) void dilated_gated(
    const float* __restrict__ hin, float* __restrict__ hout,
    const float* __restrict__ gateW, const float* __restrict__ gateB,
    const float* __restrict__ filtW, const float* __restrict__ filtB,
    const float* __restrict__ scaleW, const float* __restrict__ scaleB,
    int layer, int Tin, int Tout, int d)
{
    __shared__ float xs0[128][25];
    __shared__ float xs1[128][25];
    __shared__ ULL gp0[24][12], gp1[24][12], fp0[24][12], fp1[24][12], sp[24][12];
    __shared__ ULL gb2[12], fb2[12], sb2[12];
    const int tid = threadIdx.x;
    const int b   = blockIdx.y;
    const int t0  = blockIdx.x * 128;
    const int wbase = layer * 1152;
    for (int i = tid; i < 288; i += 128) {
        int c = i / 12, p = i % 12, o = 2 * p;
        gp0[c][p] = pk2(gateW[wbase + c * 24 + o],       gateW[wbase + c * 24 + o + 1]);
        gp1[c][p] = pk2(gateW[wbase + 576 + c * 24 + o], gateW[wbase + 576 + c * 24 + o + 1]);
        fp0[c][p] = pk2(filtW[wbase + c * 24 + o],       filtW[wbase + c * 24 + o + 1]);
        fp1[c][p] = pk2(filtW[wbase + 576 + c * 24 + o], filtW[wbase + 576 + c * 24 + o + 1]);
        sp[c][p]  = pk2(scaleW[layer * 576 + c * 24 + o], scaleW[layer * 576 + c * 24 + o + 1]);
    }
    if (tid < 12) {
        gb2[tid] = pk2(gateB[layer * 24 + 2 * tid], gateB[layer * 24 + 2 * tid + 1]);
        fb2[tid] = pk2(filtB[layer * 24 + 2 * tid], filtB[layer * 24 + 2 * tid + 1]);
        sb2[tid] = pk2(scaleB[layer * 24 + 2 * tid], scaleB[layer * 24 + 2 * tid + 1]);
    }
    const float* hb = hin + (long)b * Tin * 24;
    for (int i = tid; i < 128 * 24; i += 128) {
        int r = i / 24, c = i % 24;
        int ta = t0 + r, tb = t0 + d + r;
        xs0[r][c] = (ta < Tin) ? hb[(long)ta * 24 + c] : 0.f;
        xs1[r][c] = (tb < Tin) ? hb[(long)tb * 24 + c] : 0.f;
    }
    __syncthreads();
    int t = t0 + tid;
    if (t >= Tout) return;
    ULL gA2[12], fA2[12];
#pragma unroll
    for (int p = 0; p < 12; p++) { gA2[p] = gb2[p]; fA2[p] = fb2[p]; }
#pragma unroll
    for (int c = 0; c < 24; c++) {
        ULL x0d = dup2(xs0[tid][c]);
        ULL x1d = dup2(xs1[tid][c]);
#pragma unroll
        for (int p = 0; p < 12; p++) {
            ffma2(gA2[p], x0d, gp0[c][p]);
            ffma2(gA2[p], x1d, gp1[c][p]);
            ffma2(fA2[p], x0d, fp0[c][p]);
            ffma2(fA2[p], x1d, fp1[c][p]);
        }
    }
    float z[24];
#pragma unroll
    for (int p = 0; p < 12; p++) {
        float2 g = unpk2(gA2[p]);
        float2 f = unpk2(fA2[p]);
        z[2 * p]     = sigmoidf_(g.x) * tanhf_(f.x);
        z[2 * p + 1] = sigmoidf_(g.y) * tanhf_(f.y);
    }
    ULL o2[12];
#pragma unroll
    for (int p = 0; p < 12; p++) o2[p] = sb2[p];
#pragma unroll
    for (int c = 0; c < 24; c++) {
        ULL zd = dup2(z[c]);
#pragma unroll
        for (int p = 0; p < 12; p++) ffma2(o2[p], zd, sp[c][p]);
    }
    ULL* ob = reinterpret_cast<ULL*>(hout + ((long)b * Tout + t) * 24);
#pragma unroll
    for (int p = 0; p < 12; p++) ob[p] = o2[p];
}

// ============================================================================
// Final residual add + res conv (24->128) + relu.
// ============================================================================
__global__ __launch_bounds__(128) void resconv_relu(
    const float* __restrict__ prev8, const float* __restrict__ out8,
    const float* __restrict__ resW, const float* __restrict__ resB,
    float* __restrict__ a0out)
{
    __shared__ float ss[32][25];
    __shared__ float Ws[24][128];
    __shared__ float bs[128];
    const int tid = threadIdx.x;
    const int b   = blockIdx.y;
    const int t0  = blockIdx.x * 32;
    for (int i = tid; i < 24 * 128; i += 128) Ws[i / 128][i % 128] = resW[8 * 24 * 128 + i];
    bs[tid] = resB[8 * 128 + tid];
    const float* pb = prev8 + ((long)b * 15872 + 256) * 24;
    const float* ob = out8  + (long)b * TFIN * 24;
    for (int i = tid; i < 32 * 24; i += 128) {
        int r = i / 24, c = i % 24;
        long t = t0 + r;
        ss[r][c] = pb[t * 24 + c] + ob[t * 24 + c];
    }
    __syncthreads();
    float* outb = a0out + ((long)b * TFIN + t0) * 128;
#pragma unroll 4
    for (int r = 0; r < 32; r++) {
        float a = bs[tid];
#pragma unroll
        for (int c = 0; c < 24; c++) a += ss[r][c] * Ws[c][tid];
        outb[(long)r * 128 + tid] = fmaxf(a, 0.f);
    }
}

// ============================================================================
// Softmax over last dim (256), warp per row, in place.
// ============================================================================
__global__ void softmax256(float* __restrict__ out, long rows)
{
    long warp = (((long)blockIdx.x * blockDim.x) + threadIdx.x) >> 5;
    int lane = threadIdx.x & 31;
    if (warp >= rows) return;
    float* row = out + warp * 256;
    float v[8];
    float mx = -1e30f;
#pragma unroll
    for (int j = 0; j < 8; j++) { v[j] = row[lane + 32 * j]; mx = fmaxf(mx, v[j]); }
#pragma unroll
    for (int s = 16; s > 0; s >>= 1) mx = fmaxf(mx, __shfl_xor_sync(0xffffffffu, mx, s));
    float sum = 0.f;
#pragma unroll
    for (int j = 0; j < 8; j++) { v[j] = __expf(v[j] - mx); sum += v[j]; }
#pragma unroll
    for (int s = 16; s > 0; s >>= 1) sum += __shfl_xor_sync(0xffffffffu, sum, s);
    float inv = 1.f / sum;
#pragma unroll
    for (int j = 0; j < 8; j++) row[lane + 32 * j] = v[j] * inv;
}

// ============================================================================
extern "C" void kernel_launch(void* const* d_in, const int* in_sizes, int n_in,
                              void* d_out, int out_size)
{
    const float* x        = (const float*)d_in[0];
    const float* causal_W = (const float*)d_in[1];
    const float* causal_b = (const float*)d_in[2];
    const float* gW0      = (const float*)d_in[3];
    const float* gb0      = (const float*)d_in[4];
    const float* fW0      = (const float*)d_in[5];
    const float* fb0      = (const float*)d_in[6];
    const float* sW0      = (const float*)d_in[7];
    const float* sb0      = (const float*)d_in[8];
    const float* gateW    = (const float*)d_in[9];
    const float* gateB    = (const float*)d_in[10];
    const float* filtW    = (const float*)d_in[11];
    const float* filtB    = (const float*)d_in[12];
    const float* scaleW   = (const float*)d_in[13];
    const float* scaleB   = (const float*)d_in[14];
    const float* resW     = (const float*)d_in[15];
    const float* resB     = (const float*)d_in[16];
    const float* f1W      = (const float*)d_in[17];
    const float* f1b      = (const float*)d_in[18];
    const float* f2W      = (const float*)d_in[19];
    const float* f2b      = (const float*)d_in[20];
    float* out = (float*)d_out;

    float *y1, *zgf, *hA, *hB, *a0, *a1, *wp;
    cudaGetSymbolAddress((void**)&y1,  g_y1);
    cudaGetSymbolAddress((void**)&zgf, g_zgf);
    cudaGetSymbolAddress((void**)&hA,  g_hA);
    cudaGetSymbolAddress((void**)&hB,  g_hB);
    cudaGetSymbolAddress((void**)&a0,  g_a0);
    cudaGetSymbolAddress((void**)&a1,  g_a1);
    cudaGetSymbolAddress((void**)&wp,  g_wp);

    // 1. pack gated0 weights (g|f) -> [512,48] + bias[48]
    pack_gf<<<97, 256>>>(gW0, gb0, fW0, fb0, wp);

    // 2. causal conv as GEMM (K=512 overlap trick)
    {
        dim3 g(128, 2, B_);
        gemm128<<<g, 256>>>(x, causal_W, causal_b, y1,
                            T1_, 256, 512, 256,
                            (long)T0_ * 256, (long)T1_ * 256, 0);
    }

    // 3. gated0 g/f convs as one GEMM: zgf[b,t,0:48]
    {
        dim3 g(256, 1, B_);
        gemm64<<<g, 256>>>(y1, wp, wp + 512 * 48, zgf,
                           T2_, 48, 512, 256,
                           (long)T1_ * 256, (long)T2_ * 48, 0);
    }

    // 4. gated0 activation + 1x1 -> hA
    gated0_ew<<<1024, 128>>>(zgf, sW0, sb0, hA);

    // 5. nine dilated gated layers (ping-pong hA/hB)
    int Tin = T2_;
    float* hin  = hA;
    float* hnew = hB;
    for (int i = 0; i < 9; i++) {
        int d = 2 << i;
        int Tout = Tin - d;
        dim3 g((Tout + 127) / 128, B_);
        dilated_gated<<<g, 128>>>(hin, hnew, gateW, gateB, filtW, filtB,
                                  scaleW, scaleB, i, Tin, Tout, d);
        float* tmp = hin; hin = hnew; hnew = tmp;
        Tin = Tout;
    }
    // hin = layer-8 output (T=15360), hnew = layer-7 output (T=15872)

    // 6. residual add + res conv (only res_W[8] matters) + relu -> a0
    resconv_relu<<<dim3(480, B_), 128>>>(hnew, hin, resW, resB, a0);

    // 7. f1: [122880,128] @ [128,256] + relu
    gemm128<<<dim3(960, 2, 1), 256>>>(a0, f1W, f1b, a1,
                                      B_ * TFIN, 256, 128, 128, 0, 0, 1);

    // 8. f2: [122880,256] @ [256,256] -> logits in d_out
    gemm128<<<dim3(960, 2, 1), 256>>>(a1, f2W, f2b, out,
                                      B_ * TFIN, 256, 256, 256, 0, 0, 0);

    // 9. softmax in place
    softmax256<<<15360, 256>>>(out, (long)B_ * TFIN);
}

// round 5
// speedup vs baseline: 1.8981x; 1.7421x over previous
#include <cuda_runtime.h>
#include <cuda_bf16.h>

#define B_   8
#define T0_  16384
#define T1_  16383
#define T2_  16382
#define TFIN 15360

typedef unsigned long long ULL;
typedef unsigned int uint32;

// -------- scratch (device globals; no allocation allowed) --------
__device__ __nv_bfloat16 g_xhi [(size_t)B_ * T0_ * 256];
__device__ __nv_bfloat16 g_xlo [(size_t)B_ * T0_ * 256];
__device__ __nv_bfloat16 g_y1hi[(size_t)B_ * T1_ * 256];
__device__ __nv_bfloat16 g_y1lo[(size_t)B_ * T1_ * 256];
__device__ float g_zgf[(size_t)B_ * T2_ * 48];
__device__ float g_hA [(size_t)B_ * T2_ * 24];
__device__ float g_hB [(size_t)B_ * T2_ * 24];
__device__ __nv_bfloat16 g_a0hi[(size_t)B_ * TFIN * 128];
__device__ __nv_bfloat16 g_a0lo[(size_t)B_ * TFIN * 128];
__device__ __nv_bfloat16 g_a1hi[(size_t)B_ * TFIN * 256];
__device__ __nv_bfloat16 g_a1lo[(size_t)B_ * TFIN * 256];
__device__ float g_wp [512 * 48 + 48];
// weights in k-paired bf16x2 word layout [K/2][N]
__device__ uint32 g_WcauHi[256 * 256], g_WcauLo[256 * 256];
__device__ uint32 g_Wg0Hi [256 * 48],  g_Wg0Lo [256 * 48];
__device__ uint32 g_Wf1Hi [64 * 256],  g_Wf1Lo [64 * 256];
__device__ uint32 g_Wf2Hi [128 * 256], g_Wf2Lo [128 * 256];

// -------- small helpers --------
__device__ __forceinline__ float sigmoidf_(float x) { return 1.f / (1.f + __expf(-x)); }
__device__ __forceinline__ float tanhf_(float x) {
    float e = __expf(2.f * x);
    return 1.f - 2.f / (e + 1.f);
}
__device__ __forceinline__ ULL pk2(float lo, float hi) {
    ULL r; asm("mov.b64 %0, {%1, %2};" : "=l"(r) : "f"(lo), "f"(hi)); return r;
}
__device__ __forceinline__ ULL dup2(float x) {
    ULL r; asm("mov.b64 %0, {%1, %1};" : "=l"(r) : "f"(x)); return r;
}
__device__ __forceinline__ float2 unpk2(ULL v) {
    float2 f; asm("mov.b64 {%0, %1}, %2;" : "=f"(f.x), "=f"(f.y) : "l"(v)); return f;
}
__device__ __forceinline__ void ffma2(ULL& d, ULL a, ULL b) {
    asm("fma.rn.f32x2 %0, %1, %2, %0;" : "+l"(d) : "l"(a), "l"(b));
}

// -------- cp.async --------
__device__ __forceinline__ void cp16(uint32 dst, const void* src, bool pred) {
    int sz = pred ? 16 : 0;
    asm volatile("cp.async.ca.shared.global [%0], [%1], 16, %2;"
                 :: "r"(dst), "l"(src), "r"(sz));
}
__device__ __forceinline__ void cpcommit() { asm volatile("cp.async.commit_group;"); }
template<int N> __device__ __forceinline__ void cpwait() {
    asm volatile("cp.async.wait_group %0;" :: "n"(N));
}

// -------- bf16 mma --------
__device__ __forceinline__ void mma_bf16(float* c, const uint32* a, uint32 b0, uint32 b1) {
    asm volatile(
        "mma.sync.aligned.m16n8k16.row.col.f32.bf16.bf16.f32 "
        "{%0,%1,%2,%3}, {%4,%5,%6,%7}, {%8,%9}, {%0,%1,%2,%3};"
        : "+f"(c[0]), "+f"(c[1]), "+f"(c[2]), "+f"(c[3])
        : "r"(a[0]), "r"(a[1]), "r"(a[2]), "r"(a[3]), "r"(b0), "r"(b1));
}

// ============================================================================
// Split-bf16 tensor-core GEMM: C = A*B + bias, A fp32-split (hi/lo bf16 planes),
// B fp32-split in k-paired word layout [K/2][Nreal] (word = bf16(k even)|bf16(k odd)).
// 3 mma passes: Ahi*Bhi + Ahi*Blo + Alo*Bhi.  BM=128, BK=32, 256 threads.
// OUTMODE: 0 = fp32 C; 1 = bf16 hi/lo split (Chi/Clo). ACT: relu.
// ============================================================================
template<int BN, int OUTMODE, int ACT>
__global__ __launch_bounds__(256) void gemm_mma(
    const __nv_bfloat16* __restrict__ Ahi, const __nv_bfloat16* __restrict__ Alo,
    const uint32* __restrict__ Bhi, const uint32* __restrict__ Blo,
    const float* __restrict__ bias,
    float* __restrict__ C, __nv_bfloat16* __restrict__ Chi, __nv_bfloat16* __restrict__ Clo,
    int Mrows, int Nreal, int K, int lda, int ldc, long sA, long sC)
{
    constexpr int NT   = BN / 16;     // n-tiles (8 cols each) per warp
    constexpr int BSTR = BN + 8;      // Bs row stride (words); = 8 mod 32 -> conflict free
    constexpr int ASZ  = 128 * 20;    // words per A plane
    constexpr int BSZ  = 16 * BSTR;   // words per B plane
    extern __shared__ __align__(16) uint32 sm[];

    const int tid   = threadIdx.x;
    const int wid   = tid >> 5, lane = tid & 31;
    const int warpM = wid >> 1, warpN = wid & 1;
    const int g     = lane >> 2, t = lane & 3;
    const int m0    = blockIdx.x * 128;
    const int n0    = blockIdx.y * BN;
    const __nv_bfloat16* Ah = Ahi + (long)blockIdx.z * sA;
    const __nv_bfloat16* Al = Alo + (long)blockIdx.z * sA;

    uint32 smbase;
    asm("{ .reg .u64 tmp; cvta.to.shared.u64 tmp, %1; cvt.u32.u64 %0, tmp; }"
        : "=r"(smbase) : "l"(sm));

    float acc[2][NT][4];
#pragma unroll
    for (int i = 0; i < 2; i++)
#pragma unroll
        for (int j = 0; j < NT; j++)
#pragma unroll
            for (int k = 0; k < 4; k++) acc[i][j][k] = 0.f;

    const int nk = K / 32;

    auto fill = [&](int kt) {
        const int st = kt & 1;
        const int k0 = kt * 32;
        // A planes: 512 16B-chunks each (128 rows x 4 chunks of 8 bf16)
#pragma unroll
        for (int m = 0; m < 2; m++) {
            const __nv_bfloat16* Asrc = m ? Al : Ah;
#pragma unroll
            for (int j = 0; j < 2; j++) {
                int c = tid + j * 256;
                int r = c >> 2, q = c & 3;
                int gm = m0 + r;
                uint32 d = smbase + ((st * 2 + m) * ASZ + r * 20 + q * 4) * 4;
                cp16(d, Asrc + (long)gm * lda + k0 + q * 8, gm < Mrows);
            }
        }
        // B planes: 16 p-rows x BN/4 chunks
        constexpr int CB = 16 * (BN / 4);
#pragma unroll
        for (int m = 0; m < 2; m++) {
            const uint32* Bsrc = m ? Blo : Bhi;
#pragma unroll
            for (int j = 0; j < CB / 256; j++) {
                int c = tid + j * 256;
                int p = c / (BN / 4), q = c % (BN / 4);
                int gn = n0 + q * 4;
                uint32 d = smbase + (4 * ASZ + (st * 2 + m) * BSZ + p * BSTR + q * 4) * 4;
                cp16(d, Bsrc + (long)(k0 / 2 + p) * Nreal + gn, gn < Nreal);
            }
        }
        cpcommit();
    };

    fill(0);
    for (int kt = 0; kt < nk; kt++) {
        if (kt + 1 < nk) { fill(kt + 1); cpwait<1>(); } else { cpwait<0>(); }
        __syncthreads();
        const int st = kt & 1;
        const uint32* A_h = sm + (st * 2 + 0) * ASZ;
        const uint32* A_l = sm + (st * 2 + 1) * ASZ;
        const uint32* B_h = sm + 4 * ASZ + (st * 2 + 0) * BSZ;
        const uint32* B_l = sm + 4 * ASZ + (st * 2 + 1) * BSZ;
#pragma unroll
        for (int ks = 0; ks < 2; ks++) {
            uint32 ah[2][4], al[2][4];
            const int w0 = ks * 8 + t;
#pragma unroll
            for (int mt = 0; mt < 2; mt++) {
                int rr = warpM * 32 + mt * 16 + g;
                ah[mt][0] = A_h[rr * 20 + w0];       ah[mt][1] = A_h[(rr + 8) * 20 + w0];
                ah[mt][2] = A_h[rr * 20 + w0 + 4];   ah[mt][3] = A_h[(rr + 8) * 20 + w0 + 4];
                al[mt][0] = A_l[rr * 20 + w0];       al[mt][1] = A_l[(rr + 8) * 20 + w0];
                al[mt][2] = A_l[rr * 20 + w0 + 4];   al[mt][3] = A_l[(rr + 8) * 20 + w0 + 4];
            }
#pragma unroll
            for (int nt = 0; nt < NT; nt++) {
                int nn = warpN * (NT * 8) + nt * 8 + g;
                uint32 bh0 = B_h[w0 * BSTR + nn], bh1 = B_h[(w0 + 4) * BSTR + nn];
                uint32 bl0 = B_l[w0 * BSTR + nn], bl1 = B_l[(w0 + 4) * BSTR + nn];
#pragma unroll
                for (int mt = 0; mt < 2; mt++) {
                    mma_bf16(acc[mt][nt], ah[mt], bh0, bh1);
                    mma_bf16(acc[mt][nt], ah[mt], bl0, bl1);
                    mma_bf16(acc[mt][nt], al[mt], bh0, bh1);
                }
            }
        }
        __syncthreads();
    }

    // epilogue
    const long cb = (long)blockIdx.z * sC;
#pragma unroll
    for (int mt = 0; mt < 2; mt++) {
        int gm = m0 + warpM * 32 + mt * 16 + g;
#pragma unroll
        for (int nt = 0; nt < NT; nt++) {
            int gcol = n0 + warpN * (NT * 8) + nt * 8 + 2 * t;
            if (gcol >= Nreal) continue;
            float bb0 = bias[gcol], bb1 = bias[gcol + 1];
            float v00 = acc[mt][nt][0] + bb0, v01 = acc[mt][nt][1] + bb1;
            float v10 = acc[mt][nt][2] + bb0, v11 = acc[mt][nt][3] + bb1;
            if (ACT) {
                v00 = fmaxf(v00, 0.f); v01 = fmaxf(v01, 0.f);
                v10 = fmaxf(v10, 0.f); v11 = fmaxf(v11, 0.f);
            }
            if (OUTMODE == 0) {
                if (gm < Mrows)
                    *reinterpret_cast<float2*>(&C[cb + (long)gm * ldc + gcol]) = make_float2(v00, v01);
                if (gm + 8 < Mrows)
                    *reinterpret_cast<float2*>(&C[cb + (long)(gm + 8) * ldc + gcol]) = make_float2(v10, v11);
            } else {
                if (gm < Mrows) {
                    __nv_bfloat162 h(__float2bfloat16(v00), __float2bfloat16(v01));
                    __nv_bfloat162 l(__float2bfloat16(v00 - __bfloat162float(h.x)),
                                     __float2bfloat16(v01 - __bfloat162float(h.y)));
                    *reinterpret_cast<__nv_bfloat162*>(&Chi[cb + (long)gm * ldc + gcol]) = h;
                    *reinterpret_cast<__nv_bfloat162*>(&Clo[cb + (long)gm * ldc + gcol]) = l;
                }
                if (gm + 8 < Mrows) {
                    __nv_bfloat162 h(__float2bfloat16(v10), __float2bfloat16(v11));
                    __nv_bfloat162 l(__float2bfloat16(v10 - __bfloat162float(h.x)),
                                     __float2bfloat16(v11 - __bfloat162float(h.y)));
                    *reinterpret_cast<__nv_bfloat162*>(&Chi[cb + (long)(gm + 8) * ldc + gcol]) = h;
                    *reinterpret_cast<__nv_bfloat162*>(&Clo[cb + (long)(gm + 8) * ldc + gcol]) = l;
                }
            }
        }
    }
}

// ============================================================================
// fp32 -> hi/lo bf16 split (element arrays, n % 4 == 0)
// ============================================================================
__global__ void split_bf16_vec(const float* __restrict__ s,
                               __nv_bfloat16* __restrict__ hi,
                               __nv_bfloat16* __restrict__ lo, long n)
{
    long i = ((long)blockIdx.x * 256 + threadIdx.x) * 4;
    if (i >= n) return;
    float4 v = *reinterpret_cast<const float4*>(s + i);
    __nv_bfloat16 h0 = __float2bfloat16(v.x), h1 = __float2bfloat16(v.y);
    __nv_bfloat16 h2 = __float2bfloat16(v.z), h3 = __float2bfloat16(v.w);
    __nv_bfloat16 l0 = __float2bfloat16(v.x - __bfloat162float(h0));
    __nv_bfloat16 l1 = __float2bfloat16(v.y - __bfloat162float(h1));
    __nv_bfloat16 l2 = __float2bfloat16(v.z - __bfloat162float(h2));
    __nv_bfloat16 l3 = __float2bfloat16(v.w - __bfloat162float(h3));
    reinterpret_cast<__nv_bfloat162*>(hi + i)[0] = __nv_bfloat162(h0, h1);
    reinterpret_cast<__nv_bfloat162*>(hi + i)[1] = __nv_bfloat162(h2, h3);
    reinterpret_cast<__nv_bfloat162*>(lo + i)[0] = __nv_bfloat162(l0, l1);
    reinterpret_cast<__nv_bfloat162*>(lo + i)[1] = __nv_bfloat162(l2, l3);
}

// ============================================================================
// fp32 weight [K][N] -> hi/lo k-paired words [K/2][N]
// ============================================================================
__global__ void split_pairB(const float* __restrict__ W, uint32* __restrict__ bhi,
                            uint32* __restrict__ blo, int K2, int N)
{
    int idx = blockIdx.x * 256 + threadIdx.x;
    if (idx >= K2 * N) return;
    int p = idx / N, n = idx % N;
    float w0 = W[(long)(2 * p) * N + n];
    float w1 = W[(long)(2 * p + 1) * N + n];
    __nv_bfloat16 h0 = __float2bfloat16(w0), h1 = __float2bfloat16(w1);
    __nv_bfloat16 l0 = __float2bfloat16(w0 - __bfloat162float(h0));
    __nv_bfloat16 l1 = __float2bfloat16(w1 - __bfloat162float(h1));
    __nv_bfloat162 hw(h0, h1), lw(l0, l1);
    bhi[idx] = *reinterpret_cast<uint32*>(&hw);
    blo[idx] = *reinterpret_cast<uint32*>(&lw);
}

// ============================================================================
// Pack gated0 weights: wp[k][n] = (n<24) ? gW0[k][n] : fW0[k][n-24]; bias at end.
// ============================================================================
__global__ void pack_gf(const float* __restrict__ gW, const float* __restrict__ gb,
                        const float* __restrict__ fW, const float* __restrict__ fb,
                        float* __restrict__ wp)
{
    int idx = blockIdx.x * 256 + threadIdx.x;
    if (idx < 512 * 48) {
        int k = idx / 48, n = idx % 48;
        wp[idx] = (n < 24) ? gW[k * 24 + n] : fW[k * 24 + n - 24];
    } else if (idx < 512 * 48 + 48) {
        int n = idx - 512 * 48;
        wp[idx] = (n < 24) ? gb[n] : fb[n - 24];
    }
}

// ============================================================================
// gated0 elementwise + 1x1 scale (f32x2)
// ============================================================================
__global__ __launch_bounds__(128) void gated0_ew(
    const float* __restrict__ zgf, const float* __restrict__ sW,
    const float* __restrict__ sB, float* __restrict__ h)
{
    __shared__ float zs[128][49];
    __shared__ ULL   sp[24][12];
    __shared__ ULL   sb2[12];
    const long M = (long)B_ * T2_;
    const long t0 = (long)blockIdx.x * 128;
    const int tid = threadIdx.x;
    for (int i = tid; i < 288; i += 128) {
        int c = i / 12, p = i % 12;
        sp[c][p] = pk2(sW[c * 24 + 2 * p], sW[c * 24 + 2 * p + 1]);
    }
    if (tid < 12) sb2[tid] = pk2(sB[2 * tid], sB[2 * tid + 1]);
    for (int i = tid; i < 128 * 48; i += 128) {
        int r = i / 48, c = i % 48;
        long t = t0 + r;
        zs[r][c] = (t < M) ? zgf[t * 48 + c] : 0.f;
    }
    __syncthreads();
    long t = t0 + tid;
    if (t >= M) return;
    float z[24];
#pragma unroll
    for (int c = 0; c < 24; c++)
        z[c] = sigmoidf_(zs[tid][c]) * tanhf_(zs[tid][24 + c]);
    ULL o2[12];
#pragma unroll
    for (int p = 0; p < 12; p++) o2[p] = sb2[p];
#pragma unroll
    for (int c = 0; c < 24; c++) {
        ULL zd = dup2(z[c]);
#pragma unroll
        for (int p = 0; p < 12; p++) ffma2(o2[p], zd, sp[c][p]);
    }
    ULL* ob = reinterpret_cast<ULL*>(h + t * 24);
#pragma unroll
    for (int p = 0; p < 12; p++) ob[p] = o2[p];
}

// ============================================================================
// Fused dilated gated layer (24 ch, f32x2)
// ============================================================================
__global__ __launch_bounds__(128) void dilated_gated(
    const float* __restrict__ hin, float* __restrict__ hout,
    const float* __restrict__ gateW, const float* __restrict__ gateB,
    const float* __restrict__ filtW, const float* __restrict__ filtB,
    const float* __restrict__ scaleW, const float* __restrict__ scaleB,
    int layer, int Tin, int Tout, int d)
{
    __shared__ float xs0[128][25];
    __shared__ float xs1[128][25];
    __shared__ ULL gp0[24][12], gp1[24][12], fp0[24][12], fp1[24][12], sp[24][12];
    __shared__ ULL gb2[12], fb2[12], sb2[12];
    const int tid = threadIdx.x;
    const int b   = blockIdx.y;
    const int t0  = blockIdx.x * 128;
    const int wbase = layer * 1152;
    for (int i = tid; i < 288; i += 128) {
        int c = i / 12, p = i % 12, o = 2 * p;
        gp0[c][p] = pk2(gateW[wbase + c * 24 + o],       gateW[wbase + c * 24 + o + 1]);
        gp1[c][p] = pk2(gateW[wbase + 576 + c * 24 + o], gateW[wbase + 576 + c * 24 + o + 1]);
        fp0[c][p] = pk2(filtW[wbase + c * 24 + o],       filtW[wbase + c * 24 + o + 1]);
        fp1[c][p] = pk2(filtW[wbase + 576 + c * 24 + o], filtW[wbase + 576 + c * 24 + o + 1]);
        sp[c][p]  = pk2(scaleW[layer * 576 + c * 24 + o], scaleW[layer * 576 + c * 24 + o + 1]);
    }
    if (tid < 12) {
        gb2[tid] = pk2(gateB[layer * 24 + 2 * tid], gateB[layer * 24 + 2 * tid + 1]);
        fb2[tid] = pk2(filtB[layer * 24 + 2 * tid], filtB[layer * 24 + 2 * tid + 1]);
        sb2[tid] = pk2(scaleB[layer * 24 + 2 * tid], scaleB[layer * 24 + 2 * tid + 1]);
    }
    const float* hb = hin + (long)b * Tin * 24;
    for (int i = tid; i < 128 * 24; i += 128) {
        int r = i / 24, c = i % 24;
        int ta = t0 + r, tb = t0 + d + r;
        xs0[r][c] = (ta < Tin) ? hb[(long)ta * 24 + c] : 0.f;
        xs1[r][c] = (tb < Tin) ? hb[(long)tb * 24 + c] : 0.f;
    }
    __syncthreads();
    int t = t0 + tid;
    if (t >= Tout) return;
    ULL gA2[12], fA2[12];
#pragma unroll
    for (int p = 0; p < 12; p++) { gA2[p] = gb2[p]; fA2[p] = fb2[p]; }
#pragma unroll
    for (int c = 0; c < 24; c++) {
        ULL x0d = dup2(xs0[tid][c]);
        ULL x1d = dup2(xs1[tid][c]);
#pragma unroll
        for (int p = 0; p < 12; p++) {
            ffma2(gA2[p], x0d, gp0[c][p]);
            ffma2(gA2[p], x1d, gp1[c][p]);
            ffma2(fA2[p], x0d, fp0[c][p]);
            ffma2(fA2[p], x1d, fp1[c][p]);
        }
    }
    float z[24];
#pragma unroll
    for (int p = 0; p < 12; p++) {
        float2 gv = unpk2(gA2[p]);
        float2 fv = unpk2(fA2[p]);
        z[2 * p]     = sigmoidf_(gv.x) * tanhf_(fv.x);
        z[2 * p + 1] = sigmoidf_(gv.y) * tanhf_(fv.y);
    }
    ULL o2[12];
#pragma unroll
    for (int p = 0; p < 12; p++) o2[p] = sb2[p];
#pragma unroll
    for (int c = 0; c < 24; c++) {
        ULL zd = dup2(z[c]);
#pragma unroll
        for (int p = 0; p < 12; p++) ffma2(o2[p], zd, sp[c][p]);
    }
    ULL* ob = reinterpret_cast<ULL*>(hout + ((long)b * Tout + t) * 24);
#pragma unroll
    for (int p = 0; p < 12; p++) ob[p] = o2[p];
}

// ============================================================================
// Final residual add + res conv (24->128) + relu -> a0 as bf16 hi/lo split
// ============================================================================
__global__ __launch_bounds__(128) void resconv_relu(
    const float* __restrict__ prev8, const float* __restrict__ out8,
    const float* __restrict__ resW, const float* __restrict__ resB,
    __nv_bfloat16* __restrict__ a0hi, __nv_bfloat16* __restrict__ a0lo)
{
    __shared__ float ss[32][25];
    __shared__ float Ws[24][128];
    __shared__ float bs[128];
    const int tid = threadIdx.x;
    const int b   = blockIdx.y;
    const int t0  = blockIdx.x * 32;
    for (int i = tid; i < 24 * 128; i += 128) Ws[i / 128][i % 128] = resW[8 * 24 * 128 + i];
    bs[tid] = resB[8 * 128 + tid];
    const float* pb = prev8 + ((long)b * 15872 + 256) * 24;
    const float* ob = out8  + (long)b * TFIN * 24;
    for (int i = tid; i < 32 * 24; i += 128) {
        int r = i / 24, c = i % 24;
        long t = t0 + r;
        ss[r][c] = pb[t * 24 + c] + ob[t * 24 + c];
    }
    __syncthreads();
    long obase = ((long)b * TFIN + t0) * 128;
#pragma unroll 4
    for (int r = 0; r < 32; r++) {
        float a = bs[tid];
#pragma unroll
        for (int c = 0; c < 24; c++) a += ss[r][c] * Ws[c][tid];
        a = fmaxf(a, 0.f);
        __nv_bfloat16 h = __float2bfloat16(a);
        __nv_bfloat16 l = __float2bfloat16(a - __bfloat162float(h));
        a0hi[obase + (long)r * 128 + tid] = h;
        a0lo[obase + (long)r * 128 + tid] = l;
    }
}

// ============================================================================
// Softmax over last dim (256), warp per row, in place.
// ============================================================================
__global__ void softmax256(float* __restrict__ out, long rows)
{
    long warp = (((long)blockIdx.x * blockDim.x) + threadIdx.x) >> 5;
    int lane = threadIdx.x & 31;
    if (warp >= rows) return;
    float* row = out + warp * 256;
    float v[8];
    float mx = -1e30f;
#pragma unroll
    for (int j = 0; j < 8; j++) { v[j] = row[lane + 32 * j]; mx = fmaxf(mx, v[j]); }
#pragma unroll
    for (int s = 16; s > 0; s >>= 1) mx = fmaxf(mx, __shfl_xor_sync(0xffffffffu, mx, s));
    float sum = 0.f;
#pragma unroll
    for (int j = 0; j < 8; j++) { v[j] = __expf(v[j] - mx); sum += v[j]; }
#pragma unroll
    for (int s = 16; s > 0; s >>= 1) sum += __shfl_xor_sync(0xffffffffu, sum, s);
    float inv = 1.f / sum;
#pragma unroll
    for (int j = 0; j < 8; j++) row[lane + 32 * j] = v[j] * inv;
}

// ============================================================================
extern "C" void kernel_launch(void* const* d_in, const int* in_sizes, int n_in,
                              void* d_out, int out_size)
{
    const float* x        = (const float*)d_in[0];
    const float* causal_W = (const float*)d_in[1];
    const float* causal_b = (const float*)d_in[2];
    const float* gW0      = (const float*)d_in[3];
    const float* gb0      = (const float*)d_in[4];
    const float* fW0      = (const float*)d_in[5];
    const float* fb0      = (const float*)d_in[6];
    const float* sW0      = (const float*)d_in[7];
    const float* sb0      = (const float*)d_in[8];
    const float* gateW    = (const float*)d_in[9];
    const float* gateB    = (const float*)d_in[10];
    const float* filtW    = (const float*)d_in[11];
    const float* filtB    = (const float*)d_in[12];
    const float* scaleW   = (const float*)d_in[13];
    const float* scaleB   = (const float*)d_in[14];
    const float* resW     = (const float*)d_in[15];
    const float* resB     = (const float*)d_in[16];
    const float* f1W      = (const float*)d_in[17];
    const float* f1b      = (const float*)d_in[18];
    const float* f2W      = (const float*)d_in[19];
    const float* f2b      = (const float*)d_in[20];
    float* out = (float*)d_out;

    __nv_bfloat16 *xhi, *xlo, *y1hi, *y1lo, *a0hi, *a0lo, *a1hi, *a1lo;
    float *zgf, *hA, *hB, *wp;
    uint32 *WcauHi, *WcauLo, *Wg0Hi, *Wg0Lo, *Wf1Hi, *Wf1Lo, *Wf2Hi, *Wf2Lo;
    cudaGetSymbolAddress((void**)&xhi,  g_xhi);  cudaGetSymbolAddress((void**)&xlo,  g_xlo);
    cudaGetSymbolAddress((void**)&y1hi, g_y1hi); cudaGetSymbolAddress((void**)&y1lo, g_y1lo);
    cudaGetSymbolAddress((void**)&zgf,  g_zgf);
    cudaGetSymbolAddress((void**)&hA,   g_hA);   cudaGetSymbolAddress((void**)&hB,   g_hB);
    cudaGetSymbolAddress((void**)&a0hi, g_a0hi); cudaGetSymbolAddress((void**)&a0lo, g_a0lo);
    cudaGetSymbolAddress((void**)&a1hi, g_a1hi); cudaGetSymbolAddress((void**)&a1lo, g_a1lo);
    cudaGetSymbolAddress((void**)&wp,   g_wp);
    cudaGetSymbolAddress((void**)&WcauHi, g_WcauHi); cudaGetSymbolAddress((void**)&WcauLo, g_WcauLo);
    cudaGetSymbolAddress((void**)&Wg0Hi,  g_Wg0Hi);  cudaGetSymbolAddress((void**)&Wg0Lo,  g_Wg0Lo);
    cudaGetSymbolAddress((void**)&Wf1Hi,  g_Wf1Hi);  cudaGetSymbolAddress((void**)&Wf1Lo,  g_Wf1Lo);
    cudaGetSymbolAddress((void**)&Wf2Hi,  g_Wf2Hi);  cudaGetSymbolAddress((void**)&Wf2Lo,  g_Wf2Lo);

    const int SMEM128 = (4 * 128 * 20 + 4 * 16 * 136) * 4;  // 75776 B
    const int SMEM64  = (4 * 128 * 20 + 4 * 16 * 72) * 4;   // 59392 B
    cudaFuncSetAttribute((const void*)gemm_mma<128,1,0>, cudaFuncAttributeMaxDynamicSharedMemorySize, SMEM128);
    cudaFuncSetAttribute((const void*)gemm_mma<128,1,1>, cudaFuncAttributeMaxDynamicSharedMemorySize, SMEM128);
    cudaFuncSetAttribute((const void*)gemm_mma<128,0,0>, cudaFuncAttributeMaxDynamicSharedMemorySize, SMEM128);
    cudaFuncSetAttribute((const void*)gemm_mma<64,0,0>,  cudaFuncAttributeMaxDynamicSharedMemorySize, SMEM64);

    // 0. preprocessing: splits + packing
    long nx = (long)B_ * T0_ * 256;
    split_bf16_vec<<<(int)(nx / 4 / 256), 256>>>(x, xhi, xlo, nx);
    split_pairB<<<(256 * 256 + 255) / 256, 256>>>(causal_W, WcauHi, WcauLo, 256, 256);
    pack_gf<<<97, 256>>>(gW0, gb0, fW0, fb0, wp);
    split_pairB<<<(256 * 48 + 255) / 256, 256>>>(wp, Wg0Hi, Wg0Lo, 256, 48);
    split_pairB<<<(64 * 256 + 255) / 256, 256>>>(f1W, Wf1Hi, Wf1Lo, 64, 256);
    split_pairB<<<(128 * 256 + 255) / 256, 256>>>(f2W, Wf2Hi, Wf2Lo, 128, 256);

    // 1. causal conv as split-bf16 GEMM (K=512 overlap trick), out y1 hi/lo
    gemm_mma<128,1,0><<<dim3(128, 2, B_), 256, SMEM128>>>(
        xhi, xlo, WcauHi, WcauLo, causal_b, nullptr, y1hi, y1lo,
        T1_, 256, 512, 256, 256, (long)T0_ * 256, (long)T1_ * 256);

    // 2. gated0 g/f convs: zgf fp32 [.,48]
    gemm_mma<64,0,0><<<dim3(128, 1, B_), 256, SMEM64>>>(
        y1hi, y1lo, Wg0Hi, Wg0Lo, wp + 512 * 48, zgf, nullptr, nullptr,
        T2_, 48, 512, 256, 48, (long)T1_ * 256, (long)T2_ * 48);

    // 3. gated0 activation + 1x1 -> hA
    gated0_ew<<<1024, 128>>>(zgf, sW0, sb0, hA);

    // 4. nine dilated gated layers (ping-pong hA/hB)
    int Tin = T2_;
    float* hin  = hA;
    float* hnew = hB;
    for (int i = 0; i < 9; i++) {
        int d = 2 << i;
        int Tout = Tin - d;
        dim3 g((Tout + 127) / 128, B_);
        dilated_gated<<<g, 128>>>(hin, hnew, gateW, gateB, filtW, filtB,
                                  scaleW, scaleB, i, Tin, Tout, d);
        float* tmp = hin; hin = hnew; hnew = tmp;
        Tin = Tout;
    }
    // hin = layer-8 output (T=15360), hnew = layer-7 output (T=15872)

    // 5. residual add + res conv (only res_W[8] matters) + relu -> a0 hi/lo
    resconv_relu<<<dim3(480, B_), 128>>>(hnew, hin, resW, resB, a0hi, a0lo);

    // 6. f1 + relu -> a1 hi/lo
    gemm_mma<128,1,1><<<dim3(960, 2, 1), 256, SMEM128>>>(
        a0hi, a0lo, Wf1Hi, Wf1Lo, f1b, nullptr, a1hi, a1lo,
        B_ * TFIN, 256, 128, 128, 256, 0, 0);

    // 7. f2 -> logits fp32 in d_out
    gemm_mma<128,0,0><<<dim3(960, 2, 1), 256, SMEM128>>>(
        a1hi, a1lo, Wf2Hi, Wf2Lo, f2b, out, nullptr, nullptr,
        B_ * TFIN, 256, 256, 256, 256, 0, 0);

    // 8. softmax in place
    softmax256<<<15360, 256>>>(out, (long)B_ * TFIN);
}

// round 6
// speedup vs baseline: 1.9610x; 1.0331x over previous
#include <cuda_runtime.h>
#include <cuda_bf16.h>

#define B_   8
#define T0_  16384
#define T1_  16383
#define T2_  16382
#define TFIN 15360

typedef unsigned long long ULL;
typedef unsigned int uint32;

// -------- scratch (device globals; no allocation allowed) --------
__device__ __nv_bfloat16 g_xhi [(size_t)B_ * T0_ * 256];
__device__ __nv_bfloat16 g_xlo [(size_t)B_ * T0_ * 256];
__device__ __nv_bfloat16 g_y1hi[(size_t)B_ * T1_ * 256];
__device__ __nv_bfloat16 g_y1lo[(size_t)B_ * T1_ * 256];
__device__ float g_zgf[(size_t)B_ * T2_ * 48];
__device__ float g_hA [(size_t)B_ * T2_ * 24];
__device__ float g_hB [(size_t)B_ * T2_ * 24];
__device__ __nv_bfloat16 g_a0hi[(size_t)B_ * TFIN * 128];
__device__ __nv_bfloat16 g_a0lo[(size_t)B_ * TFIN * 128];
__device__ __nv_bfloat16 g_a1hi[(size_t)B_ * TFIN * 256];
__device__ __nv_bfloat16 g_a1lo[(size_t)B_ * TFIN * 256];
__device__ float g_wp [512 * 48 + 48];
// weights in k-paired bf16x2 word layout [K/2][N]
__device__ uint32 g_WcauHi[256 * 256], g_WcauLo[256 * 256];
__device__ uint32 g_Wg0Hi [256 * 48],  g_Wg0Lo [256 * 48];
__device__ uint32 g_Wf1Hi [64 * 256],  g_Wf1Lo [64 * 256];
__device__ uint32 g_Wf2Hi [128 * 256], g_Wf2Lo [128 * 256];

// -------- small helpers --------
__device__ __forceinline__ float sigmoidf_(float x) { return 1.f / (1.f + __expf(-x)); }
__device__ __forceinline__ float tanhf_(float x) {
    float e = __expf(2.f * x);
    return 1.f - 2.f / (e + 1.f);
}
__device__ __forceinline__ ULL pk2(float lo, float hi) {
    ULL r; asm("mov.b64 %0, {%1, %2};" : "=l"(r) : "f"(lo), "f"(hi)); return r;
}
__device__ __forceinline__ ULL dup2(float x) {
    ULL r; asm("mov.b64 %0, {%1, %1};" : "=l"(r) : "f"(x)); return r;
}
__device__ __forceinline__ float2 unpk2(ULL v) {
    float2 f; asm("mov.b64 {%0, %1}, %2;" : "=f"(f.x), "=f"(f.y) : "l"(v)); return f;
}
__device__ __forceinline__ void ffma2(ULL& d, ULL a, ULL b) {
    asm("fma.rn.f32x2 %0, %1, %2, %0;" : "+l"(d) : "l"(a), "l"(b));
}

// -------- cp.async --------
__device__ __forceinline__ void cp16(uint32 dst, const void* src, bool pred) {
    int sz = pred ? 16 : 0;
    asm volatile("cp.async.ca.shared.global [%0], [%1], 16, %2;"
                 :: "r"(dst), "l"(src), "r"(sz));
}
__device__ __forceinline__ void cpcommit() { asm volatile("cp.async.commit_group;"); }
template<int N> __device__ __forceinline__ void cpwait() {
    asm volatile("cp.async.wait_group %0;" :: "n"(N));
}

// -------- bf16 mma + ldmatrix --------
__device__ __forceinline__ void mma_bf16(float* c, const uint32* a, uint32 b0, uint32 b1) {
    asm volatile(
        "mma.sync.aligned.m16n8k16.row.col.f32.bf16.bf16.f32 "
        "{%0,%1,%2,%3}, {%4,%5,%6,%7}, {%8,%9}, {%0,%1,%2,%3};"
        : "+f"(c[0]), "+f"(c[1]), "+f"(c[2]), "+f"(c[3])
        : "r"(a[0]), "r"(a[1]), "r"(a[2]), "r"(a[3]), "r"(b0), "r"(b1));
}
__device__ __forceinline__ void ldmx4(uint32* r, uint32 addr) {
    asm volatile("ldmatrix.sync.aligned.m8n8.x4.shared.b16 {%0,%1,%2,%3}, [%4];"
                 : "=r"(r[0]), "=r"(r[1]), "=r"(r[2]), "=r"(r[3]) : "r"(addr));
}

// ============================================================================
// BIG split-bf16 tensor-core GEMM. BM=256, BN=128, BK=32, 256 threads,
// 8 warps as 4(M)x2(N); warp tile 64x64 (mt=4 x16rows, nt=8 x8cols).
// A fragments via ldmatrix.x4 from row-major smem (stride 40 halves, conflict
// free); B in k-paired word layout [K/2][N] (stride BN+8 words, conflict free).
// 3 mma passes: Ahi*Bhi + Ahi*Blo + Alo*Bhi.
// OUTMODE: 0 = fp32 C; 1 = bf16 hi/lo split. ACT: relu.
// ============================================================================
template<int OUTMODE, int ACT>
__global__ __launch_bounds__(256, 1) void gemm_big(
    const __nv_bfloat16* __restrict__ Ahi, const __nv_bfloat16* __restrict__ Alo,
    const uint32* __restrict__ Bhi, const uint32* __restrict__ Blo,
    const float* __restrict__ bias,
    float* __restrict__ C, __nv_bfloat16* __restrict__ Chi, __nv_bfloat16* __restrict__ Clo,
    int Mrows, int Nreal, int K, int lda, int ldc, long sA, long sC)
{
    constexpr int ASTR = 40;          // A row stride in halves (32 data + 8 pad)
    constexpr int APL  = 256 * ASTR;  // halves per A plane-stage
    constexpr int AW   = 4 * APL / 2; // total A words (4 plane-stages)
    constexpr int BSTR = 136;         // B row stride (words)
    constexpr int BPL  = 16 * BSTR;   // words per B plane-stage
    extern __shared__ __align__(16) uint32 sm[];

    const int tid   = threadIdx.x;
    const int wid   = tid >> 5, lane = tid & 31;
    const int warpM = wid >> 1, warpN = wid & 1;
    const int g     = lane >> 2, t = lane & 3;
    const int m0    = blockIdx.x * 256;
    const int n0    = blockIdx.y * 128;
    const __nv_bfloat16* Ah = Ahi + (long)blockIdx.z * sA;
    const __nv_bfloat16* Al = Alo + (long)blockIdx.z * sA;

    uint32 smbase;
    asm("{ .reg .u64 tmp; cvta.to.shared.u64 tmp, %1; cvt.u32.u64 %0, tmp; }"
        : "=r"(smbase) : "l"(sm));

    float acc[4][8][4];
#pragma unroll
    for (int i = 0; i < 4; i++)
#pragma unroll
        for (int j = 0; j < 8; j++)
#pragma unroll
            for (int k = 0; k < 4; k++) acc[i][j][k] = 0.f;

    const int nk = K / 32;

    auto fill = [&](int kt) {
        const int st = kt & 1;
        const int k0 = kt * 32;
        // A planes: 256 rows x 4 chunks(16B) each plane
#pragma unroll
        for (int m = 0; m < 2; m++) {
            const __nv_bfloat16* Asrc = m ? Al : Ah;
#pragma unroll
            for (int j = 0; j < 4; j++) {
                int c = tid + j * 256;
                int r = c >> 2, q = c & 3;
                int gm = m0 + r;
                uint32 d = smbase + ((st * 2 + m) * APL + r * ASTR + q * 8) * 2;
                cp16(d, Asrc + (long)gm * lda + k0 + q * 8, gm < Mrows);
            }
        }
        // B planes: 16 pair-rows x 32 chunks(4 words) each plane
#pragma unroll
        for (int m = 0; m < 2; m++) {
            const uint32* Bsrc = m ? Blo : Bhi;
#pragma unroll
            for (int j = 0; j < 2; j++) {
                int c = tid + j * 256;
                int p = c >> 5, q = c & 31;
                uint32 d = smbase + (AW + (st * 2 + m) * BPL + p * BSTR + q * 4) * 4;
                cp16(d, Bsrc + (long)(k0 / 2 + p) * Nreal + n0 + q * 4, true);
            }
        }
        cpcommit();
    };

    fill(0);
    for (int kt = 0; kt < nk; kt++) {
        if (kt + 1 < nk) { fill(kt + 1); cpwait<1>(); } else { cpwait<0>(); }
        __syncthreads();
        const int st = kt & 1;
        const uint32 aBaseH = smbase + ((st * 2 + 0) * APL) * 2;
        const uint32 aBaseL = smbase + ((st * 2 + 1) * APL) * 2;
        const uint32* B_h = sm + AW + (st * 2 + 0) * BPL;
        const uint32* B_l = sm + AW + (st * 2 + 1) * BPL;
        const int arow = warpM * 64 + (lane & 15);
        const int acol = (lane >> 4) * 8;
#pragma unroll
        for (int ks = 0; ks < 2; ks++) {
            uint32 ah[4][4], al[4][4];
            const int khalf = ks * 16 + acol;
#pragma unroll
            for (int mt = 0; mt < 4; mt++) {
                uint32 off = ((arow + mt * 16) * ASTR + khalf) * 2;
                ldmx4(ah[mt], aBaseH + off);
                ldmx4(al[mt], aBaseL + off);
            }
            const int w0 = ks * 8 + t;
#pragma unroll
            for (int nt = 0; nt < 8; nt++) {
                int nn = warpN * 64 + nt * 8 + g;
                uint32 bh0 = B_h[w0 * BSTR + nn], bh1 = B_h[(w0 + 4) * BSTR + nn];
                uint32 bl0 = B_l[w0 * BSTR + nn], bl1 = B_l[(w0 + 4) * BSTR + nn];
#pragma unroll
                for (int mt = 0; mt < 4; mt++) {
                    mma_bf16(acc[mt][nt], ah[mt], bh0, bh1);
                    mma_bf16(acc[mt][nt], ah[mt], bl0, bl1);
                    mma_bf16(acc[mt][nt], al[mt], bh0, bh1);
                }
            }
        }
        __syncthreads();
    }

    // epilogue
    const long cb = (long)blockIdx.z * sC;
#pragma unroll
    for (int mt = 0; mt < 4; mt++) {
        int gm = m0 + warpM * 64 + mt * 16 + g;
#pragma unroll
        for (int nt = 0; nt < 8; nt++) {
            int gcol = n0 + warpN * 64 + nt * 8 + 2 * t;
            float bb0 = bias[gcol], bb1 = bias[gcol + 1];
            float v00 = acc[mt][nt][0] + bb0, v01 = acc[mt][nt][1] + bb1;
            float v10 = acc[mt][nt][2] + bb0, v11 = acc[mt][nt][3] + bb1;
            if (ACT) {
                v00 = fmaxf(v00, 0.f); v01 = fmaxf(v01, 0.f);
                v10 = fmaxf(v10, 0.f); v11 = fmaxf(v11, 0.f);
            }
            if (OUTMODE == 0) {
                if (gm < Mrows)
                    *reinterpret_cast<float2*>(&C[cb + (long)gm * ldc + gcol]) = make_float2(v00, v01);
                if (gm + 8 < Mrows)
                    *reinterpret_cast<float2*>(&C[cb + (long)(gm + 8) * ldc + gcol]) = make_float2(v10, v11);
            } else {
                if (gm < Mrows) {
                    __nv_bfloat162 h(__float2bfloat16(v00), __float2bfloat16(v01));
                    __nv_bfloat162 l(__float2bfloat16(v00 - __bfloat162float(h.x)),
                                     __float2bfloat16(v01 - __bfloat162float(h.y)));
                    *reinterpret_cast<__nv_bfloat162*>(&Chi[cb + (long)gm * ldc + gcol]) = h;
                    *reinterpret_cast<__nv_bfloat162*>(&Clo[cb + (long)gm * ldc + gcol]) = l;
                }
                if (gm + 8 < Mrows) {
                    __nv_bfloat162 h(__float2bfloat16(v10), __float2bfloat16(v11));
                    __nv_bfloat162 l(__float2bfloat16(v10 - __bfloat162float(h.x)),
                                     __float2bfloat16(v11 - __bfloat162float(h.y)));
                    *reinterpret_cast<__nv_bfloat162*>(&Chi[cb + (long)(gm + 8) * ldc + gcol]) = h;
                    *reinterpret_cast<__nv_bfloat162*>(&Clo[cb + (long)(gm + 8) * ldc + gcol]) = l;
                }
            }
        }
    }
}

// ============================================================================
// Small split-bf16 GEMM (BM=128, BN=64, guarded N) -- used for gated0 (N=48).
// (unchanged from R5; known-good)
// ============================================================================
template<int BN, int OUTMODE, int ACT>
__global__ __launch_bounds__(256) void gemm_mma(
    const __nv_bfloat16* __restrict__ Ahi, const __nv_bfloat16* __restrict__ Alo,
    const uint32* __restrict__ Bhi, const uint32* __restrict__ Blo,
    const float* __restrict__ bias,
    float* __restrict__ C, __nv_bfloat16* __restrict__ Chi, __nv_bfloat16* __restrict__ Clo,
    int Mrows, int Nreal, int K, int lda, int ldc, long sA, long sC)
{
    constexpr int NT   = BN / 16;
    constexpr int BSTR = BN + 8;
    constexpr int ASZ  = 128 * 20;
    constexpr int BSZ  = 16 * BSTR;
    extern __shared__ __align__(16) uint32 sm[];

    const int tid   = threadIdx.x;
    const int wid   = tid >> 5, lane = tid & 31;
    const int warpM = wid >> 1, warpN = wid & 1;
    const int g     = lane >> 2, t = lane & 3;
    const int m0    = blockIdx.x * 128;
    const int n0    = blockIdx.y * BN;
    const __nv_bfloat16* Ah = Ahi + (long)blockIdx.z * sA;
    const __nv_bfloat16* Al = Alo + (long)blockIdx.z * sA;

    uint32 smbase;
    asm("{ .reg .u64 tmp; cvta.to.shared.u64 tmp, %1; cvt.u32.u64 %0, tmp; }"
        : "=r"(smbase) : "l"(sm));

    float acc[2][NT][4];
#pragma unroll
    for (int i = 0; i < 2; i++)
#pragma unroll
        for (int j = 0; j < NT; j++)
#pragma unroll
            for (int k = 0; k < 4; k++) acc[i][j][k] = 0.f;

    const int nk = K / 32;

    auto fill = [&](int kt) {
        const int st = kt & 1;
        const int k0 = kt * 32;
#pragma unroll
        for (int m = 0; m < 2; m++) {
            const __nv_bfloat16* Asrc = m ? Al : Ah;
#pragma unroll
            for (int j = 0; j < 2; j++) {
                int c = tid + j * 256;
                int r = c >> 2, q = c & 3;
                int gm = m0 + r;
                uint32 d = smbase + ((st * 2 + m) * ASZ + r * 20 + q * 4) * 4;
                cp16(d, Asrc + (long)gm * lda + k0 + q * 8, gm < Mrows);
            }
        }
        constexpr int CB = 16 * (BN / 4);
#pragma unroll
        for (int m = 0; m < 2; m++) {
            const uint32* Bsrc = m ? Blo : Bhi;
#pragma unroll
            for (int j = 0; j < CB / 256; j++) {
                int c = tid + j * 256;
                int p = c / (BN / 4), q = c % (BN / 4);
                int gn = n0 + q * 4;
                uint32 d = smbase + (4 * ASZ + (st * 2 + m) * BSZ + p * BSTR + q * 4) * 4;
                cp16(d, Bsrc + (long)(k0 / 2 + p) * Nreal + gn, gn < Nreal);
            }
        }
        cpcommit();
    };

    fill(0);
    for (int kt = 0; kt < nk; kt++) {
        if (kt + 1 < nk) { fill(kt + 1); cpwait<1>(); } else { cpwait<0>(); }
        __syncthreads();
        const int st = kt & 1;
        const uint32* A_h = sm + (st * 2 + 0) * ASZ;
        const uint32* A_l = sm + (st * 2 + 1) * ASZ;
        const uint32* B_h = sm + 4 * ASZ + (st * 2 + 0) * BSZ;
        const uint32* B_l = sm + 4 * ASZ + (st * 2 + 1) * BSZ;
#pragma unroll
        for (int ks = 0; ks < 2; ks++) {
            uint32 ah[2][4], al[2][4];
            const int w0 = ks * 8 + t;
#pragma unroll
            for (int mt = 0; mt < 2; mt++) {
                int rr = warpM * 32 + mt * 16 + g;
                ah[mt][0] = A_h[rr * 20 + w0];       ah[mt][1] = A_h[(rr + 8) * 20 + w0];
                ah[mt][2] = A_h[rr * 20 + w0 + 4];   ah[mt][3] = A_h[(rr + 8) * 20 + w0 + 4];
                al[mt][0] = A_l[rr * 20 + w0];       al[mt][1] = A_l[(rr + 8) * 20 + w0];
                al[mt][2] = A_l[rr * 20 + w0 + 4];   al[mt][3] = A_l[(rr + 8) * 20 + w0 + 4];
            }
#pragma unroll
            for (int nt = 0; nt < NT; nt++) {
                int nn = warpN * (NT * 8) + nt * 8 + g;
                uint32 bh0 = B_h[w0 * BSTR + nn], bh1 = B_h[(w0 + 4) * BSTR + nn];
                uint32 bl0 = B_l[w0 * BSTR + nn], bl1 = B_l[(w0 + 4) * BSTR + nn];
#pragma unroll
                for (int mt = 0; mt < 2; mt++) {
                    mma_bf16(acc[mt][nt], ah[mt], bh0, bh1);
                    mma_bf16(acc[mt][nt], ah[mt], bl0, bl1);
                    mma_bf16(acc[mt][nt], al[mt], bh0, bh1);
                }
            }
        }
        __syncthreads();
    }

    const long cb = (long)blockIdx.z * sC;
#pragma unroll
    for (int mt = 0; mt < 2; mt++) {
        int gm = m0 + warpM * 32 + mt * 16 + g;
#pragma unroll
        for (int nt = 0; nt < NT; nt++) {
            int gcol = n0 + warpN * (NT * 8) + nt * 8 + 2 * t;
            if (gcol >= Nreal) continue;
            float bb0 = bias[gcol], bb1 = bias[gcol + 1];
            float v00 = acc[mt][nt][0] + bb0, v01 = acc[mt][nt][1] + bb1;
            float v10 = acc[mt][nt][2] + bb0, v11 = acc[mt][nt][3] + bb1;
            if (ACT) {
                v00 = fmaxf(v00, 0.f); v01 = fmaxf(v01, 0.f);
                v10 = fmaxf(v10, 0.f); v11 = fmaxf(v11, 0.f);
            }
            if (OUTMODE == 0) {
                if (gm < Mrows)
                    *reinterpret_cast<float2*>(&C[cb + (long)gm * ldc + gcol]) = make_float2(v00, v01);
                if (gm + 8 < Mrows)
                    *reinterpret_cast<float2*>(&C[cb + (long)(gm + 8) * ldc + gcol]) = make_float2(v10, v11);
            }
        }
    }
}

// ============================================================================
// fp32 -> hi/lo bf16 split (element arrays, n % 4 == 0)
// ============================================================================
__global__ void split_bf16_vec(const float* __restrict__ s,
                               __nv_bfloat16* __restrict__ hi,
                               __nv_bfloat16* __restrict__ lo, long n)
{
    long i = ((long)blockIdx.x * 256 + threadIdx.x) * 4;
    if (i >= n) return;
    float4 v = *reinterpret_cast<const float4*>(s + i);
    __nv_bfloat16 h0 = __float2bfloat16(v.x), h1 = __float2bfloat16(v.y);
    __nv_bfloat16 h2 = __float2bfloat16(v.z), h3 = __float2bfloat16(v.w);
    __nv_bfloat16 l0 = __float2bfloat16(v.x - __bfloat162float(h0));
    __nv_bfloat16 l1 = __float2bfloat16(v.y - __bfloat162float(h1));
    __nv_bfloat16 l2 = __float2bfloat16(v.z - __bfloat162float(h2));
    __nv_bfloat16 l3 = __float2bfloat16(v.w - __bfloat162float(h3));
    reinterpret_cast<__nv_bfloat162*>(hi + i)[0] = __nv_bfloat162(h0, h1);
    reinterpret_cast<__nv_bfloat162*>(hi + i)[1] = __nv_bfloat162(h2, h3);
    reinterpret_cast<__nv_bfloat162*>(lo + i)[0] = __nv_bfloat162(l0, l1);
    reinterpret_cast<__nv_bfloat162*>(lo + i)[1] = __nv_bfloat162(l2, l3);
}

// ============================================================================
// fp32 weight [K][N] -> hi/lo k-paired words [K/2][N]
// ============================================================================
__global__ void split_pairB(const float* __restrict__ W, uint32* __restrict__ bhi,
                            uint32* __restrict__ blo, int K2, int N)
{
    int idx = blockIdx.x * 256 + threadIdx.x;
    if (idx >= K2 * N) return;
    int p = idx / N, n = idx % N;
    float w0 = W[(long)(2 * p) * N + n];
    float w1 = W[(long)(2 * p + 1) * N + n];
    __nv_bfloat16 h0 = __float2bfloat16(w0), h1 = __float2bfloat16(w1);
    __nv_bfloat16 l0 = __float2bfloat16(w0 - __bfloat162float(h0));
    __nv_bfloat16 l1 = __float2bfloat16(w1 - __bfloat162float(h1));
    __nv_bfloat162 hw(h0, h1), lw(l0, l1);
    bhi[idx] = *reinterpret_cast<uint32*>(&hw);
    blo[idx] = *reinterpret_cast<uint32*>(&lw);
}

// ============================================================================
// Pack gated0 weights: wp[k][n] = (n<24) ? gW0[k][n] : fW0[k][n-24]; bias end.
// ============================================================================
__global__ void pack_gf(const float* __restrict__ gW, const float* __restrict__ gb,
                        const float* __restrict__ fW, const float* __restrict__ fb,
                        float* __restrict__ wp)
{
    int idx = blockIdx.x * 256 + threadIdx.x;
    if (idx < 512 * 48) {
        int k = idx / 48, n = idx % 48;
        wp[idx] = (n < 24) ? gW[k * 24 + n] : fW[k * 24 + n - 24];
    } else if (idx < 512 * 48 + 48) {
        int n = idx - 512 * 48;
        wp[idx] = (n < 24) ? gb[n] : fb[n - 24];
    }
}

// ============================================================================
// gated0 elementwise + 1x1 scale (f32x2)
// ============================================================================
__global__ __launch_bounds__(128) void gated0_ew(
    const float* __restrict__ zgf, const float* __restrict__ sW,
    const float* __restrict__ sB, float* __restrict__ h)
{
    __shared__ float zs[128][49];
    __shared__ ULL   sp[24][12];
    __shared__ ULL   sb2[12];
    const long M = (long)B_ * T2_;
    const long t0 = (long)blockIdx.x * 128;
    const int tid = threadIdx.x;
    for (int i = tid; i < 288; i += 128) {
        int c = i / 12, p = i % 12;
        sp[c][p] = pk2(sW[c * 24 + 2 * p], sW[c * 24 + 2 * p + 1]);
    }
    if (tid < 12) sb2[tid] = pk2(sB[2 * tid], sB[2 * tid + 1]);
    for (int i = tid; i < 128 * 48; i += 128) {
        int r = i / 48, c = i % 48;
        long t = t0 + r;
        zs[r][c] = (t < M) ? zgf[t * 48 + c] : 0.f;
    }
    __syncthreads();
    long t = t0 + tid;
    if (t >= M) return;
    float z[24];
#pragma unroll
    for (int c = 0; c < 24; c++)
        z[c] = sigmoidf_(zs[tid][c]) * tanhf_(zs[tid][24 + c]);
    ULL o2[12];
#pragma unroll
    for (int p = 0; p < 12; p++) o2[p] = sb2[p];
#pragma unroll
    for (int c = 0; c < 24; c++) {
        ULL zd = dup2(z[c]);
#pragma unroll
        for (int p = 0; p < 12; p++) ffma2(o2[p], zd, sp[c][p]);
    }
    ULL* ob = reinterpret_cast<ULL*>(h + t * 24);
#pragma unroll
    for (int p = 0; p < 12; p++) ob[p] = o2[p];
}

// ============================================================================
// Fused dilated gated layer (24 ch, f32x2); processes TILES tiles per CTA
// to amortize the weight-smem prologue.
// ============================================================================
#define DG_TILES 2
__global__ __launch_bounds__(128) void dilated_gated(
    const float* __restrict__ hin, float* __restrict__ hout,
    const float* __restrict__ gateW, const float* __restrict__ gateB,
    const float* __restrict__ filtW, const float* __restrict__ filtB,
    const float* __restrict__ scaleW, const float* __restrict__ scaleB,
    int layer, int Tin, int Tout, int d)
{
    __shared__ float xs0[128][25];
    __shared__ float xs1[128][25];
    __shared__ ULL gp0[24][12], gp1[24][12], fp0[24][12], fp1[24][12], sp[24][12];
    __shared__ ULL gb2[12], fb2[12], sb2[12];
    const int tid = threadIdx.x;
    const int b   = blockIdx.y;
    const int wbase = layer * 1152;
    for (int i = tid; i < 288; i += 128) {
        int c = i / 12, p = i % 12, o = 2 * p;
        gp0[c][p] = pk2(gateW[wbase + c * 24 + o],       gateW[wbase + c * 24 + o + 1]);
        gp1[c][p] = pk2(gateW[wbase + 576 + c * 24 + o], gateW[wbase + 576 + c * 24 + o + 1]);
        fp0[c][p] = pk2(filtW[wbase + c * 24 + o],       filtW[wbase + c * 24 + o + 1]);
        fp1[c][p] = pk2(filtW[wbase + 576 + c * 24 + o], filtW[wbase + 576 + c * 24 + o + 1]);
        sp[c][p]  = pk2(scaleW[layer * 576 + c * 24 + o], scaleW[layer * 576 + c * 24 + o + 1]);
    }
    if (tid < 12) {
        gb2[tid] = pk2(gateB[layer * 24 + 2 * tid], gateB[layer * 24 + 2 * tid + 1]);
        fb2[tid] = pk2(filtB[layer * 24 + 2 * tid], filtB[layer * 24 + 2 * tid + 1]);
        sb2[tid] = pk2(scaleB[layer * 24 + 2 * tid], scaleB[layer * 24 + 2 * tid + 1]);
    }
    const float* hb = hin + (long)b * Tin * 24;
    const int nTiles = (Tout + 127) >> 7;

    for (int it = 0; it < DG_TILES; it++) {
        int tb = blockIdx.x * DG_TILES + it;
        if (tb >= nTiles) break;
        const int t0 = tb * 128;
        __syncthreads();
        for (int i = tid; i < 128 * 24; i += 128) {
            int r = i / 24, c = i % 24;
            int ta = t0 + r, tc = t0 + d + r;
            xs0[r][c] = (ta < Tin) ? hb[(long)ta * 24 + c] : 0.f;
            xs1[r][c] = (tc < Tin) ? hb[(long)tc * 24 + c] : 0.f;
        }
        __syncthreads();
        int t = t0 + tid;
        if (t >= Tout) continue;
        ULL gA2[12], fA2[12];
#pragma unroll
        for (int p = 0; p < 12; p++) { gA2[p] = gb2[p]; fA2[p] = fb2[p]; }
#pragma unroll
        for (int c = 0; c < 24; c++) {
            ULL x0d = dup2(xs0[tid][c]);
            ULL x1d = dup2(xs1[tid][c]);
#pragma unroll
            for (int p = 0; p < 12; p++) {
                ffma2(gA2[p], x0d, gp0[c][p]);
                ffma2(gA2[p], x1d, gp1[c][p]);
                ffma2(fA2[p], x0d, fp0[c][p]);
                ffma2(fA2[p], x1d, fp1[c][p]);
            }
        }
        float z[24];
#pragma unroll
        for (int p = 0; p < 12; p++) {
            float2 gv = unpk2(gA2[p]);
            float2 fv = unpk2(fA2[p]);
            z[2 * p]     = sigmoidf_(gv.x) * tanhf_(fv.x);
            z[2 * p + 1] = sigmoidf_(gv.y) * tanhf_(fv.y);
        }
        ULL o2[12];
#pragma unroll
        for (int p = 0; p < 12; p++) o2[p] = sb2[p];
#pragma unroll
        for (int c = 0; c < 24; c++) {
            ULL zd = dup2(z[c]);
#pragma unroll
            for (int p = 0; p < 12; p++) ffma2(o2[p], zd, sp[c][p]);
        }
        ULL* ob = reinterpret_cast<ULL*>(hout + ((long)b * Tout + t) * 24);
#pragma unroll
        for (int p = 0; p < 12; p++) ob[p] = o2[p];
    }
}

// ============================================================================
// Final residual add + res conv (24->128) + relu -> a0 as bf16 hi/lo split
// ============================================================================
__global__ __launch_bounds__(128) void resconv_relu(
    const float* __restrict__ prev8, const float* __restrict__ out8,
    const float* __restrict__ resW, const float* __restrict__ resB,
    __nv_bfloat16* __restrict__ a0hi, __nv_bfloat16* __restrict__ a0lo)
{
    __shared__ float ss[32][25];
    __shared__ float Ws[24][128];
    __shared__ float bs[128];
    const int tid = threadIdx.x;
    const int b   = blockIdx.y;
    const int t0  = blockIdx.x * 32;
    for (int i = tid; i < 24 * 128; i += 128) Ws[i / 128][i % 128] = resW[8 * 24 * 128 + i];
    bs[tid] = resB[8 * 128 + tid];
    const float* pb = prev8 + ((long)b * 15872 + 256) * 24;
    const float* ob = out8  + (long)b * TFIN * 24;
    for (int i = tid; i < 32 * 24; i += 128) {
        int r = i / 24, c = i % 24;
        long t = t0 + r;
        ss[r][c] = pb[t * 24 + c] + ob[t * 24 + c];
    }
    __syncthreads();
    long obase = ((long)b * TFIN + t0) * 128;
#pragma unroll 4
    for (int r = 0; r < 32; r++) {
        float a = bs[tid];
#pragma unroll
        for (int c = 0; c < 24; c++) a += ss[r][c] * Ws[c][tid];
        a = fmaxf(a, 0.f);
        __nv_bfloat16 h = __float2bfloat16(a);
        __nv_bfloat16 l = __float2bfloat16(a - __bfloat162float(h));
        a0hi[obase + (long)r * 128 + tid] = h;
        a0lo[obase + (long)r * 128 + tid] = l;
    }
}

// ============================================================================
// Softmax over last dim (256), warp per row, in place.
// ============================================================================
__global__ void softmax256(float* __restrict__ out, long rows)
{
    long warp = (((long)blockIdx.x * blockDim.x) + threadIdx.x) >> 5;
    int lane = threadIdx.x & 31;
    if (warp >= rows) return;
    float* row = out + warp * 256;
    float v[8];
    float mx = -1e30f;
#pragma unroll
    for (int j = 0; j < 8; j++) { v[j] = row[lane + 32 * j]; mx = fmaxf(mx, v[j]); }
#pragma unroll
    for (int s = 16; s > 0; s >>= 1) mx = fmaxf(mx, __shfl_xor_sync(0xffffffffu, mx, s));
    float sum = 0.f;
#pragma unroll
    for (int j = 0; j < 8; j++) { v[j] = __expf(v[j] - mx); sum += v[j]; }
#pragma unroll
    for (int s = 16; s > 0; s >>= 1) sum += __shfl_xor_sync(0xffffffffu, sum, s);
    float inv = 1.f / sum;
#pragma unroll
    for (int j = 0; j < 8; j++) row[lane + 32 * j] = v[j] * inv;
}

// ============================================================================
extern "C" void kernel_launch(void* const* d_in, const int* in_sizes, int n_in,
                              void* d_out, int out_size)
{
    const float* x        = (const float*)d_in[0];
    const float* causal_W = (const float*)d_in[1];
    const float* causal_b = (const float*)d_in[2];
    const float* gW0      = (const float*)d_in[3];
    const float* gb0      = (const float*)d_in[4];
    const float* fW0      = (const float*)d_in[5];
    const float* fb0      = (const float*)d_in[6];
    const float* sW0      = (const float*)d_in[7];
    const float* sb0      = (const float*)d_in[8];
    const float* gateW    = (const float*)d_in[9];
    const float* gateB    = (const float*)d_in[10];
    const float* filtW    = (const float*)d_in[11];
    const float* filtB    = (const float*)d_in[12];
    const float* scaleW   = (const float*)d_in[13];
    const float* scaleB   = (const float*)d_in[14];
    const float* resW     = (const float*)d_in[15];
    const float* resB     = (const float*)d_in[16];
    const float* f1W      = (const float*)d_in[17];
    const float* f1b      = (const float*)d_in[18];
    const float* f2W      = (const float*)d_in[19];
    const float* f2b      = (const float*)d_in[20];
    float* out = (float*)d_out;

    __nv_bfloat16 *xhi, *xlo, *y1hi, *y1lo, *a0hi, *a0lo, *a1hi, *a1lo;
    float *zgf, *hA, *hB, *wp;
    uint32 *WcauHi, *WcauLo, *Wg0Hi, *Wg0Lo, *Wf1Hi, *Wf1Lo, *Wf2Hi, *Wf2Lo;
    cudaGetSymbolAddress((void**)&xhi,  g_xhi);  cudaGetSymbolAddress((void**)&xlo,  g_xlo);
    cudaGetSymbolAddress((void**)&y1hi, g_y1hi); cudaGetSymbolAddress((void**)&y1lo, g_y1lo);
    cudaGetSymbolAddress((void**)&zgf,  g_zgf);
    cudaGetSymbolAddress((void**)&hA,   g_hA);   cudaGetSymbolAddress((void**)&hB,   g_hB);
    cudaGetSymbolAddress((void**)&a0hi, g_a0hi); cudaGetSymbolAddress((void**)&a0lo, g_a0lo);
    cudaGetSymbolAddress((void**)&a1hi, g_a1hi); cudaGetSymbolAddress((void**)&a1lo, g_a1lo);
    cudaGetSymbolAddress((void**)&wp,   g_wp);
    cudaGetSymbolAddress((void**)&WcauHi, g_WcauHi); cudaGetSymbolAddress((void**)&WcauLo, g_WcauLo);
    cudaGetSymbolAddress((void**)&Wg0Hi,  g_Wg0Hi);  cudaGetSymbolAddress((void**)&Wg0Lo,  g_Wg0Lo);
    cudaGetSymbolAddress((void**)&Wf1Hi,  g_Wf1Hi);  cudaGetSymbolAddress((void**)&Wf1Lo,  g_Wf1Lo);
    cudaGetSymbolAddress((void**)&Wf2Hi,  g_Wf2Hi);  cudaGetSymbolAddress((void**)&Wf2Lo,  g_Wf2Lo);

    const int SMEM_BIG = (4 * 256 * 40 / 2 + 4 * 16 * 136) * 4;   // 116736 B
    const int SMEM64   = (4 * 128 * 20 + 4 * 16 * 72) * 4;        // 59392 B
    cudaFuncSetAttribute((const void*)gemm_big<1,0>, cudaFuncAttributeMaxDynamicSharedMemorySize, SMEM_BIG);
    cudaFuncSetAttribute((const void*)gemm_big<1,1>, cudaFuncAttributeMaxDynamicSharedMemorySize, SMEM_BIG);
    cudaFuncSetAttribute((const void*)gemm_big<0,0>, cudaFuncAttributeMaxDynamicSharedMemorySize, SMEM_BIG);
    cudaFuncSetAttribute((const void*)gemm_mma<64,0,0>, cudaFuncAttributeMaxDynamicSharedMemorySize, SMEM64);

    // 0. preprocessing: splits + packing
    long nx = (long)B_ * T0_ * 256;
    split_bf16_vec<<<(int)(nx / 4 / 256), 256>>>(x, xhi, xlo, nx);
    split_pairB<<<(256 * 256 + 255) / 256, 256>>>(causal_W, WcauHi, WcauLo, 256, 256);
    pack_gf<<<97, 256>>>(gW0, gb0, fW0, fb0, wp);
    split_pairB<<<(256 * 48 + 255) / 256, 256>>>(wp, Wg0Hi, Wg0Lo, 256, 48);
    split_pairB<<<(64 * 256 + 255) / 256, 256>>>(f1W, Wf1Hi, Wf1Lo, 64, 256);
    split_pairB<<<(128 * 256 + 255) / 256, 256>>>(f2W, Wf2Hi, Wf2Lo, 128, 256);

    // 1. causal conv as split-bf16 GEMM (K=512 overlap trick), out y1 hi/lo
    gemm_big<1,0><<<dim3(64, 2, B_), 256, SMEM_BIG>>>(
        xhi, xlo, WcauHi, WcauLo, causal_b, nullptr, y1hi, y1lo,
        T1_, 256, 512, 256, 256, (long)T0_ * 256, (long)T1_ * 256);

    // 2. gated0 g/f convs: zgf fp32 [.,48]
    gemm_mma<64,0,0><<<dim3(128, 1, B_), 256, SMEM64>>>(
        y1hi, y1lo, Wg0Hi, Wg0Lo, wp + 512 * 48, zgf, nullptr, nullptr,
        T2_, 48, 512, 256, 48, (long)T1_ * 256, (long)T2_ * 48);

    // 3. gated0 activation + 1x1 -> hA
    gated0_ew<<<1024, 128>>>(zgf, sW0, sb0, hA);

    // 4. nine dilated gated layers (ping-pong hA/hB)
    int Tin = T2_;
    float* hin  = hA;
    float* hnew = hB;
    for (int i = 0; i < 9; i++) {
        int d = 2 << i;
        int Tout = Tin - d;
        int nTiles = (Tout + 127) / 128;
        dim3 g((nTiles + DG_TILES - 1) / DG_TILES, B_);
        dilated_gated<<<g, 128>>>(hin, hnew, gateW, gateB, filtW, filtB,
                                  scaleW, scaleB, i, Tin, Tout, d);
        float* tmp = hin; hin = hnew; hnew = tmp;
        Tin = Tout;
    }
    // hin = layer-8 output (T=15360), hnew = layer-7 output (T=15872)

    // 5. residual add + res conv (only res_W[8] matters) + relu -> a0 hi/lo
    resconv_relu<<<dim3(480, B_), 128>>>(hnew, hin, resW, resB, a0hi, a0lo);

    // 6. f1 + relu -> a1 hi/lo
    gemm_big<1,1><<<dim3(480, 2, 1), 256, SMEM_BIG>>>(
        a0hi, a0lo, Wf1Hi, Wf1Lo, f1b, nullptr, a1hi, a1lo,
        B_ * TFIN, 256, 128, 128, 256, 0, 0);

    // 7. f2 -> logits fp32 in d_out
    gemm_big<0,0><<<dim3(480, 2, 1), 256, SMEM_BIG>>>(
        a1hi, a1lo, Wf2Hi, Wf2Lo, f2b, out, nullptr, nullptr,
        B_ * TFIN, 256, 256, 256, 256, 0, 0);

    // 8. softmax in place
    softmax256<<<15360, 256>>>(out, (long)B_ * TFIN);
}

// round 7
// speedup vs baseline: 2.0649x; 1.0530x over previous
#include <cuda_runtime.h>
#include <cuda_bf16.h>

#define B_   8
#define T0_  16384
#define T1_  16383
#define T2_  16382
#define TFIN 15360

typedef unsigned long long ULL;
typedef unsigned int uint32;

// -------- scratch (device globals; no allocation allowed) --------
__device__ __nv_bfloat16 g_xhi [(size_t)B_ * T0_ * 256];
__device__ __nv_bfloat16 g_xlo [(size_t)B_ * T0_ * 256];
__device__ __nv_bfloat16 g_y1hi[(size_t)B_ * T1_ * 256];
__device__ __nv_bfloat16 g_y1lo[(size_t)B_ * T1_ * 256];
__device__ float g_zgf[(size_t)B_ * T2_ * 48];
__device__ float g_hA [(size_t)B_ * T2_ * 24];
__device__ float g_hB [(size_t)B_ * T2_ * 24];
__device__ __nv_bfloat16 g_a0hi[(size_t)B_ * TFIN * 128];
__device__ __nv_bfloat16 g_a0lo[(size_t)B_ * TFIN * 128];
__device__ __nv_bfloat16 g_a1hi[(size_t)B_ * TFIN * 256];
__device__ __nv_bfloat16 g_a1lo[(size_t)B_ * TFIN * 256];
__device__ float g_wp [512 * 48 + 48];
// weights in k-paired bf16x2 word layout [K/2][N]
__device__ uint32 g_WcauHi[256 * 256], g_WcauLo[256 * 256];
__device__ uint32 g_Wg0Hi [256 * 48],  g_Wg0Lo [256 * 48];
__device__ uint32 g_Wf1Hi [64 * 256],  g_Wf1Lo [64 * 256];
__device__ uint32 g_Wf2Hi [128 * 256], g_Wf2Lo [128 * 256];

// -------- small helpers --------
__device__ __forceinline__ float sigmoidf_(float x) { return 1.f / (1.f + __expf(-x)); }
__device__ __forceinline__ float tanhf_(float x) {
    float e = __expf(2.f * x);
    return 1.f - 2.f / (e + 1.f);
}
__device__ __forceinline__ ULL pk2(float lo, float hi) {
    ULL r; asm("mov.b64 %0, {%1, %2};" : "=l"(r) : "f"(lo), "f"(hi)); return r;
}
__device__ __forceinline__ ULL dup2(float x) {
    ULL r; asm("mov.b64 %0, {%1, %1};" : "=l"(r) : "f"(x)); return r;
}
__device__ __forceinline__ float2 unpk2(ULL v) {
    float2 f; asm("mov.b64 {%0, %1}, %2;" : "=f"(f.x), "=f"(f.y) : "l"(v)); return f;
}
__device__ __forceinline__ void ffma2(ULL& d, ULL a, ULL b) {
    asm("fma.rn.f32x2 %0, %1, %2, %0;" : "+l"(d) : "l"(a), "l"(b));
}

// -------- cp.async --------
__device__ __forceinline__ void cp16(uint32 dst, const void* src, bool pred) {
    int sz = pred ? 16 : 0;
    asm volatile("cp.async.ca.shared.global [%0], [%1], 16, %2;"
                 :: "r"(dst), "l"(src), "r"(sz));
}
__device__ __forceinline__ void cpcommit() { asm volatile("cp.async.commit_group;"); }
template<int N> __device__ __forceinline__ void cpwait() {
    asm volatile("cp.async.wait_group %0;" :: "n"(N));
}

// -------- bf16 mma + ldmatrix --------
__device__ __forceinline__ void mma_bf16(float* c, const uint32* a, uint32 b0, uint32 b1) {
    asm volatile(
        "mma.sync.aligned.m16n8k16.row.col.f32.bf16.bf16.f32 "
        "{%0,%1,%2,%3}, {%4,%5,%6,%7}, {%8,%9}, {%0,%1,%2,%3};"
        : "+f"(c[0]), "+f"(c[1]), "+f"(c[2]), "+f"(c[3])
        : "r"(a[0]), "r"(a[1]), "r"(a[2]), "r"(a[3]), "r"(b0), "r"(b1));
}
__device__ __forceinline__ void ldmx4(uint32* r, uint32 addr) {
    asm volatile("ldmatrix.sync.aligned.m8n8.x4.shared.b16 {%0,%1,%2,%3}, [%4];"
                 : "=r"(r[0]), "=r"(r[1]), "=r"(r[2]), "=r"(r[3]) : "r"(addr));
}

// ============================================================================
// N256 split-bf16 GEMM: BM=128, BN=256 (full row per CTA), BK=32, 3-stage
// cp.async pipeline, 256 threads = 8 warps as 2(M)x4(N), warp tile 64x64.
// 3 mma passes: Ahi*Bhi + Ahi*Blo + Alo*Bhi.
// OUTMODE: 0 = fp32 C; 1 = bf16 hi/lo split.  ACT: relu.  SOFTMAX: fused
// exact fp32 softmax over the 256 columns (requires OUTMODE=0).
// ============================================================================
template<int OUTMODE, int ACT, int SOFTMAX>
__global__ __launch_bounds__(256, 1) void gemm_n256(
    const __nv_bfloat16* __restrict__ Ahi, const __nv_bfloat16* __restrict__ Alo,
    const uint32* __restrict__ Bhi, const uint32* __restrict__ Blo,
    const float* __restrict__ bias,
    float* __restrict__ C, __nv_bfloat16* __restrict__ Chi, __nv_bfloat16* __restrict__ Clo,
    int Mrows, int K, int lda, long sA, long sC)
{
    constexpr int NREAL = 256;
    constexpr int ASTR = 40;              // A row stride (halves)
    constexpr int APLW = 128 * ASTR / 2;  // words per A plane-stage = 2560
    constexpr int AW   = 6 * APLW;        // 3 stages x 2 planes
    constexpr int BSTR = 264;             // B row stride (words)
    constexpr int BPL  = 16 * BSTR;       // words per B plane-stage = 4224
    extern __shared__ __align__(16) uint32 sm[];
    __shared__ float red[128][4];

    const int tid   = threadIdx.x;
    const int wid   = tid >> 5, lane = tid & 31;
    const int warpM = wid >> 2, warpN = wid & 3;
    const int g     = lane >> 2, t = lane & 3;
    const int m0    = blockIdx.x * 128;
    const __nv_bfloat16* Ah = Ahi + (long)blockIdx.z * sA;
    const __nv_bfloat16* Al = Alo + (long)blockIdx.z * sA;

    uint32 smbase;
    asm("{ .reg .u64 tmp; cvta.to.shared.u64 tmp, %1; cvt.u32.u64 %0, tmp; }"
        : "=r"(smbase) : "l"(sm));

    float acc[4][8][4];
#pragma unroll
    for (int i = 0; i < 4; i++)
#pragma unroll
        for (int j = 0; j < 8; j++)
#pragma unroll
            for (int k = 0; k < 4; k++) acc[i][j][k] = 0.f;

    const int nk = K / 32;

    auto fill = [&](int kt) {
        const int st = kt % 3;
        const int k0 = kt * 32;
        // A: 2 planes x 512 chunks (128 rows x 4 chunks of 8 bf16)
#pragma unroll
        for (int m = 0; m < 2; m++) {
            const __nv_bfloat16* Asrc = m ? Al : Ah;
#pragma unroll
            for (int j = 0; j < 2; j++) {
                int c = tid + j * 256;
                int r = c >> 2, q = c & 3;
                int gm = m0 + r;
                uint32 d = smbase + ((st * 2 + m) * APLW + r * 20 + q * 4) * 4;
                cp16(d, Asrc + (long)gm * lda + k0 + q * 8, gm < Mrows);
            }
        }
        // B: 2 planes x 1024 chunks (16 pair-rows x 64 chunks of 4 words)
#pragma unroll
        for (int m = 0; m < 2; m++) {
            const uint32* Bsrc = m ? Blo : Bhi;
#pragma unroll
            for (int j = 0; j < 4; j++) {
                int c = tid + j * 256;
                int p = c >> 6, q = c & 63;
                uint32 d = smbase + (AW + (st * 2 + m) * BPL + p * BSTR + q * 4) * 4;
                cp16(d, Bsrc + (long)(k0 / 2 + p) * NREAL + q * 4, true);
            }
        }
        cpcommit();
    };

    fill(0);
    fill(1);
    for (int kt = 0; kt < nk; kt++) {
        if (kt + 2 < nk) { fill(kt + 2); cpwait<2>(); }
        else if (kt + 1 < nk) { cpwait<1>(); }
        else { cpwait<0>(); }
        __syncthreads();
        const int st = kt % 3;
        const uint32 aBaseH = smbase + ((st * 2 + 0) * APLW) * 4;
        const uint32 aBaseL = smbase + ((st * 2 + 1) * APLW) * 4;
        const uint32* B_h = sm + AW + (st * 2 + 0) * BPL;
        const uint32* B_l = sm + AW + (st * 2 + 1) * BPL;
        const int arow = warpM * 64 + (lane & 15);
        const int acol = (lane >> 4) * 8;
#pragma unroll
        for (int ks = 0; ks < 2; ks++) {
            uint32 ah[4][4], al[4][4];
            const int khalf = ks * 16 + acol;
#pragma unroll
            for (int mt = 0; mt < 4; mt++) {
                uint32 off = ((arow + mt * 16) * ASTR + khalf) * 2;
                ldmx4(ah[mt], aBaseH + off);
                ldmx4(al[mt], aBaseL + off);
            }
            const int w0 = ks * 8 + t;
#pragma unroll
            for (int nt = 0; nt < 8; nt++) {
                int nn = warpN * 64 + nt * 8 + g;
                uint32 bh0 = B_h[w0 * BSTR + nn], bh1 = B_h[(w0 + 4) * BSTR + nn];
                uint32 bl0 = B_l[w0 * BSTR + nn], bl1 = B_l[(w0 + 4) * BSTR + nn];
#pragma unroll
                for (int mt = 0; mt < 4; mt++) {
                    mma_bf16(acc[mt][nt], ah[mt], bh0, bh1);
                    mma_bf16(acc[mt][nt], ah[mt], bl0, bl1);
                    mma_bf16(acc[mt][nt], al[mt], bh0, bh1);
                }
            }
        }
        __syncthreads();
    }

    // ---- epilogue ----
    const long cb = (long)blockIdx.z * sC;

    // bias (+relu)
#pragma unroll
    for (int mt = 0; mt < 4; mt++)
#pragma unroll
        for (int nt = 0; nt < 8; nt++) {
            int gcol = warpN * 64 + nt * 8 + 2 * t;
            float bb0 = bias[gcol], bb1 = bias[gcol + 1];
            acc[mt][nt][0] += bb0; acc[mt][nt][1] += bb1;
            acc[mt][nt][2] += bb0; acc[mt][nt][3] += bb1;
            if (ACT) {
#pragma unroll
                for (int q = 0; q < 4; q++) acc[mt][nt][q] = fmaxf(acc[mt][nt][q], 0.f);
            }
        }

    if (SOFTMAX) {
        // exact fp32 softmax over 256 cols; rows are complete within the CTA.
        float rmax[4][2], rsum[4][2];
#pragma unroll
        for (int mt = 0; mt < 4; mt++)
#pragma unroll
            for (int h = 0; h < 2; h++) {
                float m = -1e30f;
#pragma unroll
                for (int nt = 0; nt < 8; nt++)
                    m = fmaxf(m, fmaxf(acc[mt][nt][2 * h], acc[mt][nt][2 * h + 1]));
                m = fmaxf(m, __shfl_xor_sync(0xffffffffu, m, 1));
                m = fmaxf(m, __shfl_xor_sync(0xffffffffu, m, 2));
                rmax[mt][h] = m;
            }
        if (t == 0)
#pragma unroll
            for (int mt = 0; mt < 4; mt++)
#pragma unroll
                for (int h = 0; h < 2; h++)
                    red[warpM * 64 + mt * 16 + g + h * 8][warpN] = rmax[mt][h];
        __syncthreads();
#pragma unroll
        for (int mt = 0; mt < 4; mt++)
#pragma unroll
            for (int h = 0; h < 2; h++) {
                int r = warpM * 64 + mt * 16 + g + h * 8;
                rmax[mt][h] = fmaxf(fmaxf(red[r][0], red[r][1]),
                                    fmaxf(red[r][2], red[r][3]));
            }
        __syncthreads();
#pragma unroll
        for (int mt = 0; mt < 4; mt++)
#pragma unroll
            for (int h = 0; h < 2; h++) {
                float s = 0.f;
#pragma unroll
                for (int nt = 0; nt < 8; nt++) {
                    float e0 = __expf(acc[mt][nt][2 * h]     - rmax[mt][h]);
                    float e1 = __expf(acc[mt][nt][2 * h + 1] - rmax[mt][h]);
                    acc[mt][nt][2 * h] = e0; acc[mt][nt][2 * h + 1] = e1;
                    s += e0 + e1;
                }
                s += __shfl_xor_sync(0xffffffffu, s, 1);
                s += __shfl_xor_sync(0xffffffffu, s, 2);
                rsum[mt][h] = s;
            }
        if (t == 0)
#pragma unroll
            for (int mt = 0; mt < 4; mt++)
#pragma unroll
                for (int h = 0; h < 2; h++)
                    red[warpM * 64 + mt * 16 + g + h * 8][warpN] = rsum[mt][h];
        __syncthreads();
#pragma unroll
        for (int mt = 0; mt < 4; mt++)
#pragma unroll
            for (int h = 0; h < 2; h++) {
                int r = warpM * 64 + mt * 16 + g + h * 8;
                float s = red[r][0] + red[r][1] + red[r][2] + red[r][3];
                float inv = 1.f / s;
#pragma unroll
                for (int nt = 0; nt < 8; nt++) {
                    acc[mt][nt][2 * h]     *= inv;
                    acc[mt][nt][2 * h + 1] *= inv;
                }
            }
    }

#pragma unroll
    for (int mt = 0; mt < 4; mt++) {
        int gm = m0 + warpM * 64 + mt * 16 + g;
#pragma unroll
        for (int nt = 0; nt < 8; nt++) {
            int gcol = warpN * 64 + nt * 8 + 2 * t;
            float v00 = acc[mt][nt][0], v01 = acc[mt][nt][1];
            float v10 = acc[mt][nt][2], v11 = acc[mt][nt][3];
            if (OUTMODE == 0) {
                if (gm < Mrows)
                    *reinterpret_cast<float2*>(&C[cb + (long)gm * NREAL + gcol]) = make_float2(v00, v01);
                if (gm + 8 < Mrows)
                    *reinterpret_cast<float2*>(&C[cb + (long)(gm + 8) * NREAL + gcol]) = make_float2(v10, v11);
            } else {
                if (gm < Mrows) {
                    __nv_bfloat162 h(__float2bfloat16(v00), __float2bfloat16(v01));
                    __nv_bfloat162 l(__float2bfloat16(v00 - __bfloat162float(h.x)),
                                     __float2bfloat16(v01 - __bfloat162float(h.y)));
                    *reinterpret_cast<__nv_bfloat162*>(&Chi[cb + (long)gm * NREAL + gcol]) = h;
                    *reinterpret_cast<__nv_bfloat162*>(&Clo[cb + (long)gm * NREAL + gcol]) = l;
                }
                if (gm + 8 < Mrows) {
                    __nv_bfloat162 h(__float2bfloat16(v10), __float2bfloat16(v11));
                    __nv_bfloat162 l(__float2bfloat16(v10 - __bfloat162float(h.x)),
                                     __float2bfloat16(v11 - __bfloat162float(h.y)));
                    *reinterpret_cast<__nv_bfloat162*>(&Chi[cb + (long)(gm + 8) * NREAL + gcol]) = h;
                    *reinterpret_cast<__nv_bfloat162*>(&Clo[cb + (long)(gm + 8) * NREAL + gcol]) = l;
                }
            }
        }
    }
}

// ============================================================================
// Small split-bf16 GEMM (BM=128, BN=64, guarded N) -- used for gated0 (N=48).
// ============================================================================
template<int BN, int OUTMODE, int ACT>
__global__ __launch_bounds__(256) void gemm_mma(
    const __nv_bfloat16* __restrict__ Ahi, const __nv_bfloat16* __restrict__ Alo,
    const uint32* __restrict__ Bhi, const uint32* __restrict__ Blo,
    const float* __restrict__ bias,
    float* __restrict__ C, __nv_bfloat16* __restrict__ Chi, __nv_bfloat16* __restrict__ Clo,
    int Mrows, int Nreal, int K, int lda, int ldc, long sA, long sC)
{
    constexpr int NT   = BN / 16;
    constexpr int BSTR = BN + 8;
    constexpr int ASZ  = 128 * 20;
    constexpr int BSZ  = 16 * BSTR;
    extern __shared__ __align__(16) uint32 sm[];

    const int tid   = threadIdx.x;
    const int wid   = tid >> 5, lane = tid & 31;
    const int warpM = wid >> 1, warpN = wid & 1;
    const int g     = lane >> 2, t = lane & 3;
    const int m0    = blockIdx.x * 128;
    const int n0    = blockIdx.y * BN;
    const __nv_bfloat16* Ah = Ahi + (long)blockIdx.z * sA;
    const __nv_bfloat16* Al = Alo + (long)blockIdx.z * sA;

    uint32 smbase;
    asm("{ .reg .u64 tmp; cvta.to.shared.u64 tmp, %1; cvt.u32.u64 %0, tmp; }"
        : "=r"(smbase) : "l"(sm));

    float acc[2][NT][4];
#pragma unroll
    for (int i = 0; i < 2; i++)
#pragma unroll
        for (int j = 0; j < NT; j++)
#pragma unroll
            for (int k = 0; k < 4; k++) acc[i][j][k] = 0.f;

    const int nk = K / 32;

    auto fill = [&](int kt) {
        const int st = kt & 1;
        const int k0 = kt * 32;
#pragma unroll
        for (int m = 0; m < 2; m++) {
            const __nv_bfloat16* Asrc = m ? Al : Ah;
#pragma unroll
            for (int j = 0; j < 2; j++) {
                int c = tid + j * 256;
                int r = c >> 2, q = c & 3;
                int gm = m0 + r;
                uint32 d = smbase + ((st * 2 + m) * ASZ + r * 20 + q * 4) * 4;
                cp16(d, Asrc + (long)gm * lda + k0 + q * 8, gm < Mrows);
            }
        }
        constexpr int CB = 16 * (BN / 4);
#pragma unroll
        for (int m = 0; m < 2; m++) {
            const uint32* Bsrc = m ? Blo : Bhi;
#pragma unroll
            for (int j = 0; j < CB / 256; j++) {
                int c = tid + j * 256;
                int p = c / (BN / 4), q = c % (BN / 4);
                int gn = n0 + q * 4;
                uint32 d = smbase + (4 * ASZ + (st * 2 + m) * BSZ + p * BSTR + q * 4) * 4;
                cp16(d, Bsrc + (long)(k0 / 2 + p) * Nreal + gn, gn < Nreal);
            }
        }
        cpcommit();
    };

    fill(0);
    for (int kt = 0; kt < nk; kt++) {
        if (kt + 1 < nk) { fill(kt + 1); cpwait<1>(); } else { cpwait<0>(); }
        __syncthreads();
        const int st = kt & 1;
        const uint32* A_h = sm + (st * 2 + 0) * ASZ;
        const uint32* A_l = sm + (st * 2 + 1) * ASZ;
        const uint32* B_h = sm + 4 * ASZ + (st * 2 + 0) * BSZ;
        const uint32* B_l = sm + 4 * ASZ + (st * 2 + 1) * BSZ;
#pragma unroll
        for (int ks = 0; ks < 2; ks++) {
            uint32 ah[2][4], al[2][4];
            const int w0 = ks * 8 + t;
#pragma unroll
            for (int mt = 0; mt < 2; mt++) {
                int rr = warpM * 32 + mt * 16 + g;
                ah[mt][0] = A_h[rr * 20 + w0];       ah[mt][1] = A_h[(rr + 8) * 20 + w0];
                ah[mt][2] = A_h[rr * 20 + w0 + 4];   ah[mt][3] = A_h[(rr + 8) * 20 + w0 + 4];
                al[mt][0] = A_l[rr * 20 + w0];       al[mt][1] = A_l[(rr + 8) * 20 + w0];
                al[mt][2] = A_l[rr * 20 + w0 + 4];   al[mt][3] = A_l[(rr + 8) * 20 + w0 + 4];
            }
#pragma unroll
            for (int nt = 0; nt < NT; nt++) {
                int nn = warpN * (NT * 8) + nt * 8 + g;
                uint32 bh0 = B_h[w0 * BSTR + nn], bh1 = B_h[(w0 + 4) * BSTR + nn];
                uint32 bl0 = B_l[w0 * BSTR + nn], bl1 = B_l[(w0 + 4) * BSTR + nn];
#pragma unroll
                for (int mt = 0; mt < 2; mt++) {
                    mma_bf16(acc[mt][nt], ah[mt], bh0, bh1);
                    mma_bf16(acc[mt][nt], ah[mt], bl0, bl1);
                    mma_bf16(acc[mt][nt], al[mt], bh0, bh1);
                }
            }
        }
        __syncthreads();
    }

    const long cb = (long)blockIdx.z * sC;
#pragma unroll
    for (int mt = 0; mt < 2; mt++) {
        int gm = m0 + warpM * 32 + mt * 16 + g;
#pragma unroll
        for (int nt = 0; nt < NT; nt++) {
            int gcol = n0 + warpN * (NT * 8) + nt * 8 + 2 * t;
            if (gcol >= Nreal) continue;
            float bb0 = bias[gcol], bb1 = bias[gcol + 1];
            float v00 = acc[mt][nt][0] + bb0, v01 = acc[mt][nt][1] + bb1;
            float v10 = acc[mt][nt][2] + bb0, v11 = acc[mt][nt][3] + bb1;
            if (ACT) {
                v00 = fmaxf(v00, 0.f); v01 = fmaxf(v01, 0.f);
                v10 = fmaxf(v10, 0.f); v11 = fmaxf(v11, 0.f);
            }
            if (OUTMODE == 0) {
                if (gm < Mrows)
                    *reinterpret_cast<float2*>(&C[cb + (long)gm * ldc + gcol]) = make_float2(v00, v01);
                if (gm + 8 < Mrows)
                    *reinterpret_cast<float2*>(&C[cb + (long)(gm + 8) * ldc + gcol]) = make_float2(v10, v11);
            }
        }
    }
}

// ============================================================================
// fp32 -> hi/lo bf16 split (element arrays, n % 4 == 0)
// ============================================================================
__global__ void split_bf16_vec(const float* __restrict__ s,
                               __nv_bfloat16* __restrict__ hi,
                               __nv_bfloat16* __restrict__ lo, long n)
{
    long i = ((long)blockIdx.x * 256 + threadIdx.x) * 4;
    if (i >= n) return;
    float4 v = *reinterpret_cast<const float4*>(s + i);
    __nv_bfloat16 h0 = __float2bfloat16(v.x), h1 = __float2bfloat16(v.y);
    __nv_bfloat16 h2 = __float2bfloat16(v.z), h3 = __float2bfloat16(v.w);
    __nv_bfloat16 l0 = __float2bfloat16(v.x - __bfloat162float(h0));
    __nv_bfloat16 l1 = __float2bfloat16(v.y - __bfloat162float(h1));
    __nv_bfloat16 l2 = __float2bfloat16(v.z - __bfloat162float(h2));
    __nv_bfloat16 l3 = __float2bfloat16(v.w - __bfloat162float(h3));
    reinterpret_cast<__nv_bfloat162*>(hi + i)[0] = __nv_bfloat162(h0, h1);
    reinterpret_cast<__nv_bfloat162*>(hi + i)[1] = __nv_bfloat162(h2, h3);
    reinterpret_cast<__nv_bfloat162*>(lo + i)[0] = __nv_bfloat162(l0, l1);
    reinterpret_cast<__nv_bfloat162*>(lo + i)[1] = __nv_bfloat162(l2, l3);
}

// ============================================================================
// fp32 weight [K][N] -> hi/lo k-paired words [K/2][N]
// ============================================================================
__global__ void split_pairB(const float* __restrict__ W, uint32* __restrict__ bhi,
                            uint32* __restrict__ blo, int K2, int N)
{
    int idx = blockIdx.x * 256 + threadIdx.x;
    if (idx >= K2 * N) return;
    int p = idx / N, n = idx % N;
    float w0 = W[(long)(2 * p) * N + n];
    float w1 = W[(long)(2 * p + 1) * N + n];
    __nv_bfloat16 h0 = __float2bfloat16(w0), h1 = __float2bfloat16(w1);
    __nv_bfloat16 l0 = __float2bfloat16(w0 - __bfloat162float(h0));
    __nv_bfloat16 l1 = __float2bfloat16(w1 - __bfloat162float(h1));
    __nv_bfloat162 hw(h0, h1), lw(l0, l1);
    bhi[idx] = *reinterpret_cast<uint32*>(&hw);
    blo[idx] = *reinterpret_cast<uint32*>(&lw);
}

// ============================================================================
// Pack gated0 weights: wp[k][n] = (n<24) ? gW0[k][n] : fW0[k][n-24]; bias end.
// ============================================================================
__global__ void pack_gf(const float* __restrict__ gW, const float* __restrict__ gb,
                        const float* __restrict__ fW, const float* __restrict__ fb,
                        float* __restrict__ wp)
{
    int idx = blockIdx.x * 256 + threadIdx.x;
    if (idx < 512 * 48) {
        int k = idx / 48, n = idx % 48;
        wp[idx] = (n < 24) ? gW[k * 24 + n] : fW[k * 24 + n - 24];
    } else if (idx < 512 * 48 + 48) {
        int n = idx - 512 * 48;
        wp[idx] = (n < 24) ? gb[n] : fb[n - 24];
    }
}

// ============================================================================
// gated0 elementwise + 1x1 scale (f32x2)
// ============================================================================
__global__ __launch_bounds__(128) void gated0_ew(
    const float* __restrict__ zgf, const float* __restrict__ sW,
    const float* __restrict__ sB, float* __restrict__ h)
{
    __shared__ float zs[128][49];
    __shared__ ULL   sp[24][12];
    __shared__ ULL   sb2[12];
    const long M = (long)B_ * T2_;
    const long t0 = (long)blockIdx.x * 128;
    const int tid = threadIdx.x;
    for (int i = tid; i < 288; i += 128) {
        int c = i / 12, p = i % 12;
        sp[c][p] = pk2(sW[c * 24 + 2 * p], sW[c * 24 + 2 * p + 1]);
    }
    if (tid < 12) sb2[tid] = pk2(sB[2 * tid], sB[2 * tid + 1]);
    for (int i = tid; i < 128 * 48; i += 128) {
        int r = i / 48, c = i % 48;
        long t = t0 + r;
        zs[r][c] = (t < M) ? zgf[t * 48 + c] : 0.f;
    }
    __syncthreads();
    long t = t0 + tid;
    if (t >= M) return;
    float z[24];
#pragma unroll
    for (int c = 0; c < 24; c++)
        z[c] = sigmoidf_(zs[tid][c]) * tanhf_(zs[tid][24 + c]);
    ULL o2[12];
#pragma unroll
    for (int p = 0; p < 12; p++) o2[p] = sb2[p];
#pragma unroll
    for (int c = 0; c < 24; c++) {
        ULL zd = dup2(z[c]);
#pragma unroll
        for (int p = 0; p < 12; p++) ffma2(o2[p], zd, sp[c][p]);
    }
    ULL* ob = reinterpret_cast<ULL*>(h + t * 24);
#pragma unroll
    for (int p = 0; p < 12; p++) ob[p] = o2[p];
}

// ============================================================================
// Fused dilated gated layer (24 ch, f32x2); DG_TILES tiles per CTA.
// ============================================================================
#define DG_TILES 2
__global__ __launch_bounds__(128) void dilated_gated(
    const float* __restrict__ hin, float* __restrict__ hout,
    const float* __restrict__ gateW, const float* __restrict__ gateB,
    const float* __restrict__ filtW, const float* __restrict__ filtB,
    const float* __restrict__ scaleW, const float* __restrict__ scaleB,
    int layer, int Tin, int Tout, int d)
{
    __shared__ float xs0[128][25];
    __shared__ float xs1[128][25];
    __shared__ ULL gp0[24][12], gp1[24][12], fp0[24][12], fp1[24][12], sp[24][12];
    __shared__ ULL gb2[12], fb2[12], sb2[12];
    const int tid = threadIdx.x;
    const int b   = blockIdx.y;
    const int wbase = layer * 1152;
    for (int i = tid; i < 288; i += 128) {
        int c = i / 12, p = i % 12, o = 2 * p;
        gp0[c][p] = pk2(gateW[wbase + c * 24 + o],       gateW[wbase + c * 24 + o + 1]);
        gp1[c][p] = pk2(gateW[wbase + 576 + c * 24 + o], gateW[wbase + 576 + c * 24 + o + 1]);
        fp0[c][p] = pk2(filtW[wbase + c * 24 + o],       filtW[wbase + c * 24 + o + 1]);
        fp1[c][p] = pk2(filtW[wbase + 576 + c * 24 + o], filtW[wbase + 576 + c * 24 + o + 1]);
        sp[c][p]  = pk2(scaleW[layer * 576 + c * 24 + o], scaleW[layer * 576 + c * 24 + o + 1]);
    }
    if (tid < 12) {
        gb2[tid] = pk2(gateB[layer * 24 + 2 * tid], gateB[layer * 24 + 2 * tid + 1]);
        fb2[tid] = pk2(filtB[layer * 24 + 2 * tid], filtB[layer * 24 + 2 * tid + 1]);
        sb2[tid] = pk2(scaleB[layer * 24 + 2 * tid], scaleB[layer * 24 + 2 * tid + 1]);
    }
    const float* hb = hin + (long)b * Tin * 24;
    const int nTiles = (Tout + 127) >> 7;

    for (int it = 0; it < DG_TILES; it++) {
        int tb = blockIdx.x * DG_TILES + it;
        if (tb >= nTiles) break;
        const int t0 = tb * 128;
        __syncthreads();
        for (int i = tid; i < 128 * 24; i += 128) {
            int r = i / 24, c = i % 24;
            int ta = t0 + r, tc = t0 + d + r;
            xs0[r][c] = (ta < Tin) ? hb[(long)ta * 24 + c] : 0.f;
            xs1[r][c] = (tc < Tin) ? hb[(long)tc * 24 + c] : 0.f;
        }
        __syncthreads();
        int t = t0 + tid;
        if (t >= Tout) continue;
        ULL gA2[12], fA2[12];
#pragma unroll
        for (int p = 0; p < 12; p++) { gA2[p] = gb2[p]; fA2[p] = fb2[p]; }
#pragma unroll
        for (int c = 0; c < 24; c++) {
            ULL x0d = dup2(xs0[tid][c]);
            ULL x1d = dup2(xs1[tid][c]);
#pragma unroll
            for (int p = 0; p < 12; p++) {
                ffma2(gA2[p], x0d, gp0[c][p]);
                ffma2(gA2[p], x1d, gp1[c][p]);
                ffma2(fA2[p], x0d, fp0[c][p]);
                ffma2(fA2[p], x1d, fp1[c][p]);
            }
        }
        float z[24];
#pragma unroll
        for (int p = 0; p < 12; p++) {
            float2 gv = unpk2(gA2[p]);
            float2 fv = unpk2(fA2[p]);
            z[2 * p]     = sigmoidf_(gv.x) * tanhf_(fv.x);
            z[2 * p + 1] = sigmoidf_(gv.y) * tanhf_(fv.y);
        }
        ULL o2[12];
#pragma unroll
        for (int p = 0; p < 12; p++) o2[p] = sb2[p];
#pragma unroll
        for (int c = 0; c < 24; c++) {
            ULL zd = dup2(z[c]);
#pragma unroll
            for (int p = 0; p < 12; p++) ffma2(o2[p], zd, sp[c][p]);
        }
        ULL* ob = reinterpret_cast<ULL*>(hout + ((long)b * Tout + t) * 24);
#pragma unroll
        for (int p = 0; p < 12; p++) ob[p] = o2[p];
    }
}

// ============================================================================
// Final residual add + res conv (24->128) + relu -> a0 as bf16 hi/lo split
// ============================================================================
__global__ __launch_bounds__(128) void resconv_relu(
    const float* __restrict__ prev8, const float* __restrict__ out8,
    const float* __restrict__ resW, const float* __restrict__ resB,
    __nv_bfloat16* __restrict__ a0hi, __nv_bfloat16* __restrict__ a0lo)
{
    __shared__ float ss[32][25];
    __shared__ float Ws[24][128];
    __shared__ float bs[128];
    const int tid = threadIdx.x;
    const int b   = blockIdx.y;
    const int t0  = blockIdx.x * 32;
    for (int i = tid; i < 24 * 128; i += 128) Ws[i / 128][i % 128] = resW[8 * 24 * 128 + i];
    bs[tid] = resB[8 * 128 + tid];
    const float* pb = prev8 + ((long)b * 15872 + 256) * 24;
    const float* ob = out8  + (long)b * TFIN * 24;
    for (int i = tid; i < 32 * 24; i += 128) {
        int r = i / 24, c = i % 24;
        long t = t0 + r;
        ss[r][c] = pb[t * 24 + c] + ob[t * 24 + c];
    }
    __syncthreads();
    long obase = ((long)b * TFIN + t0) * 128;
#pragma unroll 4
    for (int r = 0; r < 32; r++) {
        float a = bs[tid];
#pragma unroll
        for (int c = 0; c < 24; c++) a += ss[r][c] * Ws[c][tid];
        a = fmaxf(a, 0.f);
        __nv_bfloat16 h = __float2bfloat16(a);
        __nv_bfloat16 l = __float2bfloat16(a - __bfloat162float(h));
        a0hi[obase + (long)r * 128 + tid] = h;
        a0lo[obase + (long)r * 128 + tid] = l;
    }
}

// ============================================================================
extern "C" void kernel_launch(void* const* d_in, const int* in_sizes, int n_in,
                              void* d_out, int out_size)
{
    const float* x        = (const float*)d_in[0];
    const float* causal_W = (const float*)d_in[1];
    const float* causal_b = (const float*)d_in[2];
    const float* gW0      = (const float*)d_in[3];
    const float* gb0      = (const float*)d_in[4];
    const float* fW0      = (const float*)d_in[5];
    const float* fb0      = (const float*)d_in[6];
    const float* sW0      = (const float*)d_in[7];
    const float* sb0      = (const float*)d_in[8];
    const float* gateW    = (const float*)d_in[9];
    const float* gateB    = (const float*)d_in[10];
    const float* filtW    = (const float*)d_in[11];
    const float* filtB    = (const float*)d_in[12];
    const float* scaleW   = (const float*)d_in[13];
    const float* scaleB   = (const float*)d_in[14];
    const float* resW     = (const float*)d_in[15];
    const float* resB     = (const float*)d_in[16];
    const float* f1W      = (const float*)d_in[17];
    const float* f1b      = (const float*)d_in[18];
    const float* f2W      = (const float*)d_in[19];
    const float* f2b      = (const float*)d_in[20];
    float* out = (float*)d_out;

    __nv_bfloat16 *xhi, *xlo, *y1hi, *y1lo, *a0hi, *a0lo, *a1hi, *a1lo;
    float *zgf, *hA, *hB, *wp;
    uint32 *WcauHi, *WcauLo, *Wg0Hi, *Wg0Lo, *Wf1Hi, *Wf1Lo, *Wf2Hi, *Wf2Lo;
    cudaGetSymbolAddress((void**)&xhi,  g_xhi);  cudaGetSymbolAddress((void**)&xlo,  g_xlo);
    cudaGetSymbolAddress((void**)&y1hi, g_y1hi); cudaGetSymbolAddress((void**)&y1lo, g_y1lo);
    cudaGetSymbolAddress((void**)&zgf,  g_zgf);
    cudaGetSymbolAddress((void**)&hA,   g_hA);   cudaGetSymbolAddress((void**)&hB,   g_hB);
    cudaGetSymbolAddress((void**)&a0hi, g_a0hi); cudaGetSymbolAddress((void**)&a0lo, g_a0lo);
    cudaGetSymbolAddress((void**)&a1hi, g_a1hi); cudaGetSymbolAddress((void**)&a1lo, g_a1lo);
    cudaGetSymbolAddress((void**)&wp,   g_wp);
    cudaGetSymbolAddress((void**)&WcauHi, g_WcauHi); cudaGetSymbolAddress((void**)&WcauLo, g_WcauLo);
    cudaGetSymbolAddress((void**)&Wg0Hi,  g_Wg0Hi);  cudaGetSymbolAddress((void**)&Wg0Lo,  g_Wg0Lo);
    cudaGetSymbolAddress((void**)&Wf1Hi,  g_Wf1Hi);  cudaGetSymbolAddress((void**)&Wf1Lo,  g_Wf1Lo);
    cudaGetSymbolAddress((void**)&Wf2Hi,  g_Wf2Hi);  cudaGetSymbolAddress((void**)&Wf2Lo,  g_Wf2Lo);

    const int SMEM_N256 = (6 * 2560 + 6 * 16 * 264) * 4;    // 162816 B
    const int SMEM64    = (4 * 128 * 20 + 4 * 16 * 72) * 4; // 59392 B
    cudaFuncSetAttribute((const void*)gemm_n256<1,0,0>, cudaFuncAttributeMaxDynamicSharedMemorySize, SMEM_N256);
    cudaFuncSetAttribute((const void*)gemm_n256<1,1,0>, cudaFuncAttributeMaxDynamicSharedMemorySize, SMEM_N256);
    cudaFuncSetAttribute((const void*)gemm_n256<0,0,1>, cudaFuncAttributeMaxDynamicSharedMemorySize, SMEM_N256);
    cudaFuncSetAttribute((const void*)gemm_mma<64,0,0>, cudaFuncAttributeMaxDynamicSharedMemorySize, SMEM64);

    // 0. preprocessing: splits + packing
    long nx = (long)B_ * T0_ * 256;
    split_bf16_vec<<<(int)(nx / 4 / 256), 256>>>(x, xhi, xlo, nx);
    split_pairB<<<(256 * 256 + 255) / 256, 256>>>(causal_W, WcauHi, WcauLo, 256, 256);
    pack_gf<<<97, 256>>>(gW0, gb0, fW0, fb0, wp);
    split_pairB<<<(256 * 48 + 255) / 256, 256>>>(wp, Wg0Hi, Wg0Lo, 256, 48);
    split_pairB<<<(64 * 256 + 255) / 256, 256>>>(f1W, Wf1Hi, Wf1Lo, 64, 256);
    split_pairB<<<(128 * 256 + 255) / 256, 256>>>(f2W, Wf2Hi, Wf2Lo, 128, 256);

    // 1. causal conv as split-bf16 GEMM (K=512 overlap trick), out y1 hi/lo
    gemm_n256<1,0,0><<<dim3(129, 1, B_), 256, SMEM_N256>>>(
        xhi, xlo, WcauHi, WcauLo, causal_b, nullptr, y1hi, y1lo,
        T1_, 512, 256, (long)T0_ * 256, (long)T1_ * 256);

    // 2. gated0 g/f convs: zgf fp32 [.,48]
    gemm_mma<64,0,0><<<dim3(128, 1, B_), 256, SMEM64>>>(
        y1hi, y1lo, Wg0Hi, Wg0Lo, wp + 512 * 48, zgf, nullptr, nullptr,
        T2_, 48, 512, 256, 48, (long)T1_ * 256, (long)T2_ * 48);

    // 3. gated0 activation + 1x1 -> hA
    gated0_ew<<<1024, 128>>>(zgf, sW0, sb0, hA);

    // 4. nine dilated gated layers (ping-pong hA/hB)
    int Tin = T2_;
    float* hin  = hA;
    float* hnew = hB;
    for (int i = 0; i < 9; i++) {
        int d = 2 << i;
        int Tout = Tin - d;
        int nTiles = (Tout + 127) / 128;
        dim3 g((nTiles + DG_TILES - 1) / DG_TILES, B_);
        dilated_gated<<<g, 128>>>(hin, hnew, gateW, gateB, filtW, filtB,
                                  scaleW, scaleB, i, Tin, Tout, d);
        float* tmp = hin; hin = hnew; hnew = tmp;
        Tin = Tout;
    }
    // hin = layer-8 output (T=15360), hnew = layer-7 output (T=15872)

    // 5. residual add + res conv (only res_W[8] matters) + relu -> a0 hi/lo
    resconv_relu<<<dim3(480, B_), 128>>>(hnew, hin, resW, resB, a0hi, a0lo);

    // 6. f1 + relu -> a1 hi/lo
    gemm_n256<1,1,0><<<dim3(960, 1, 1), 256, SMEM_N256>>>(
        a0hi, a0lo, Wf1Hi, Wf1Lo, f1b, nullptr, a1hi, a1lo,
        B_ * TFIN, 128, 128, 0, 0);

    // 7. f2 + fused exact softmax -> probabilities fp32 in d_out
    gemm_n256<0,0,1><<<dim3(960, 1, 1), 256, SMEM_N256>>>(
        a1hi, a1lo, Wf2Hi, Wf2Lo, f2b, out, nullptr, nullptr,
        B_ * TFIN, 256, 256, 0, 0);
}

// round 8
// speedup vs baseline: 2.0872x; 1.0108x over previous
#include <cuda_runtime.h>
#include <cuda_bf16.h>

#define B_   8
#define T0_  16384
#define T1_  16383
#define T2_  16382
#define TFIN 15360

typedef unsigned long long ULL;
typedef unsigned int uint32;

// -------- scratch (device globals; no allocation allowed) --------
__device__ __nv_bfloat16 g_xhi [(size_t)B_ * T0_ * 256];
__device__ __nv_bfloat16 g_xlo [(size_t)B_ * T0_ * 256];
__device__ __nv_bfloat16 g_y1hi[(size_t)B_ * T1_ * 256];
__device__ __nv_bfloat16 g_y1lo[(size_t)B_ * T1_ * 256];
__device__ float g_hA [(size_t)B_ * T2_ * 24];
__device__ float g_hB [(size_t)B_ * T2_ * 24];
__device__ __nv_bfloat16 g_a0hi[(size_t)B_ * TFIN * 128];
__device__ __nv_bfloat16 g_a0lo[(size_t)B_ * TFIN * 128];
__device__ __nv_bfloat16 g_a1hi[(size_t)B_ * TFIN * 256];
__device__ __nv_bfloat16 g_a1lo[(size_t)B_ * TFIN * 256];
// weights in k-paired bf16x2 word layout [K/2][N]
__device__ uint32 g_WcauHi[256 * 256], g_WcauLo[256 * 256];
__device__ uint32 g_Wg0Hi [256 * 48],  g_Wg0Lo [256 * 48];
__device__ uint32 g_Wf1Hi [64 * 256],  g_Wf1Lo [64 * 256];
__device__ uint32 g_Wf2Hi [128 * 256], g_Wf2Lo [128 * 256];

// -------- small helpers --------
__device__ __forceinline__ float sigmoidf_(float x) { return 1.f / (1.f + __expf(-x)); }
__device__ __forceinline__ float tanhf_(float x) {
    float e = __expf(2.f * x);
    return 1.f - 2.f / (e + 1.f);
}
__device__ __forceinline__ ULL pk2(float lo, float hi) {
    ULL r; asm("mov.b64 %0, {%1, %2};" : "=l"(r) : "f"(lo), "f"(hi)); return r;
}
__device__ __forceinline__ ULL dup2(float x) {
    ULL r; asm("mov.b64 %0, {%1, %1};" : "=l"(r) : "f"(x)); return r;
}
__device__ __forceinline__ float2 unpk2(ULL v) {
    float2 f; asm("mov.b64 {%0, %1}, %2;" : "=f"(f.x), "=f"(f.y) : "l"(v)); return f;
}
__device__ __forceinline__ void ffma2(ULL& d, ULL a, ULL b) {
    asm("fma.rn.f32x2 %0, %1, %2, %0;" : "+l"(d) : "l"(a), "l"(b));
}

// -------- cp.async --------
__device__ __forceinline__ void cp16(uint32 dst, const void* src, bool pred) {
    int sz = pred ? 16 : 0;
    asm volatile("cp.async.ca.shared.global [%0], [%1], 16, %2;"
                 :: "r"(dst), "l"(src), "r"(sz));
}
__device__ __forceinline__ void cpcommit() { asm volatile("cp.async.commit_group;"); }
template<int N> __device__ __forceinline__ void cpwait() {
    asm volatile("cp.async.wait_group %0;" :: "n"(N));
}

// -------- bf16 mma + ldmatrix --------
__device__ __forceinline__ void mma_bf16(float* c, const uint32* a, uint32 b0, uint32 b1) {
    asm volatile(
        "mma.sync.aligned.m16n8k16.row.col.f32.bf16.bf16.f32 "
        "{%0,%1,%2,%3}, {%4,%5,%6,%7}, {%8,%9}, {%0,%1,%2,%3};"
        : "+f"(c[0]), "+f"(c[1]), "+f"(c[2]), "+f"(c[3])
        : "r"(a[0]), "r"(a[1]), "r"(a[2]), "r"(a[3]), "r"(b0), "r"(b1));
}
__device__ __forceinline__ void ldmx4(uint32* r, uint32 addr) {
    asm volatile("ldmatrix.sync.aligned.m8n8.x4.shared.b16 {%0,%1,%2,%3}, [%4];"
                 : "=r"(r[0]), "=r"(r[1]), "=r"(r[2]), "=r"(r[3]) : "r"(addr));
}

// ============================================================================
// N256 split-bf16 GEMM: BM=128, BN=256 (full row per CTA), BK=32, 3-stage
// cp.async pipeline, 256 threads = 8 warps as 2(M)x4(N), warp tile 64x64.
// 3 mma passes: Ahi*Bhi + Ahi*Blo + Alo*Bhi.
// OUTMODE: 0 = fp32 C; 1 = bf16 hi/lo split.  ACT: relu.  SOFTMAX: fused
// exact fp32 softmax over the 256 columns (requires OUTMODE=0).
// ============================================================================
template<int OUTMODE, int ACT, int SOFTMAX>
__global__ __launch_bounds__(256, 1) void gemm_n256(
    const __nv_bfloat16* __restrict__ Ahi, const __nv_bfloat16* __restrict__ Alo,
    const uint32* __restrict__ Bhi, const uint32* __restrict__ Blo,
    const float* __restrict__ bias,
    float* __restrict__ C, __nv_bfloat16* __restrict__ Chi, __nv_bfloat16* __restrict__ Clo,
    int Mrows, int K, int lda, long sA, long sC)
{
    constexpr int NREAL = 256;
    constexpr int ASTR = 40;
    constexpr int APLW = 128 * ASTR / 2;
    constexpr int AW   = 6 * APLW;
    constexpr int BSTR = 264;
    constexpr int BPL  = 16 * BSTR;
    extern __shared__ __align__(16) uint32 sm[];
    __shared__ float red[128][4];

    const int tid   = threadIdx.x;
    const int wid   = tid >> 5, lane = tid & 31;
    const int warpM = wid >> 2, warpN = wid & 3;
    const int g     = lane >> 2, t = lane & 3;
    const int m0    = blockIdx.x * 128;
    const __nv_bfloat16* Ah = Ahi + (long)blockIdx.z * sA;
    const __nv_bfloat16* Al = Alo + (long)blockIdx.z * sA;

    uint32 smbase;
    asm("{ .reg .u64 tmp; cvta.to.shared.u64 tmp, %1; cvt.u32.u64 %0, tmp; }"
        : "=r"(smbase) : "l"(sm));

    float acc[4][8][4];
#pragma unroll
    for (int i = 0; i < 4; i++)
#pragma unroll
        for (int j = 0; j < 8; j++)
#pragma unroll
            for (int k = 0; k < 4; k++) acc[i][j][k] = 0.f;

    const int nk = K / 32;

    auto fill = [&](int kt) {
        const int st = kt % 3;
        const int k0 = kt * 32;
#pragma unroll
        for (int m = 0; m < 2; m++) {
            const __nv_bfloat16* Asrc = m ? Al : Ah;
#pragma unroll
            for (int j = 0; j < 2; j++) {
                int c = tid + j * 256;
                int r = c >> 2, q = c & 3;
                int gm = m0 + r;
                uint32 d = smbase + ((st * 2 + m) * APLW + r * 20 + q * 4) * 4;
                cp16(d, Asrc + (long)gm * lda + k0 + q * 8, gm < Mrows);
            }
        }
#pragma unroll
        for (int m = 0; m < 2; m++) {
            const uint32* Bsrc = m ? Blo : Bhi;
#pragma unroll
            for (int j = 0; j < 4; j++) {
                int c = tid + j * 256;
                int p = c >> 6, q = c & 63;
                uint32 d = smbase + (AW + (st * 2 + m) * BPL + p * BSTR + q * 4) * 4;
                cp16(d, Bsrc + (long)(k0 / 2 + p) * NREAL + q * 4, true);
            }
        }
        cpcommit();
    };

    fill(0);
    fill(1);
    for (int kt = 0; kt < nk; kt++) {
        if (kt + 2 < nk) { fill(kt + 2); cpwait<2>(); }
        else if (kt + 1 < nk) { cpwait<1>(); }
        else { cpwait<0>(); }
        __syncthreads();
        const int st = kt % 3;
        const uint32 aBaseH = smbase + ((st * 2 + 0) * APLW) * 4;
        const uint32 aBaseL = smbase + ((st * 2 + 1) * APLW) * 4;
        const uint32* B_h = sm + AW + (st * 2 + 0) * BPL;
        const uint32* B_l = sm + AW + (st * 2 + 1) * BPL;
        const int arow = warpM * 64 + (lane & 15);
        const int acol = (lane >> 4) * 8;
#pragma unroll
        for (int ks = 0; ks < 2; ks++) {
            uint32 ah[4][4], al[4][4];
            const int khalf = ks * 16 + acol;
#pragma unroll
            for (int mt = 0; mt < 4; mt++) {
                uint32 off = ((arow + mt * 16) * ASTR + khalf) * 2;
                ldmx4(ah[mt], aBaseH + off);
                ldmx4(al[mt], aBaseL + off);
            }
            const int w0 = ks * 8 + t;
#pragma unroll
            for (int nt = 0; nt < 8; nt++) {
                int nn = warpN * 64 + nt * 8 + g;
                uint32 bh0 = B_h[w0 * BSTR + nn], bh1 = B_h[(w0 + 4) * BSTR + nn];
                uint32 bl0 = B_l[w0 * BSTR + nn], bl1 = B_l[(w0 + 4) * BSTR + nn];
#pragma unroll
                for (int mt = 0; mt < 4; mt++) {
                    mma_bf16(acc[mt][nt], ah[mt], bh0, bh1);
                    mma_bf16(acc[mt][nt], ah[mt], bl0, bl1);
                    mma_bf16(acc[mt][nt], al[mt], bh0, bh1);
                }
            }
        }
        __syncthreads();
    }

    // ---- epilogue ----
    const long cb = (long)blockIdx.z * sC;

#pragma unroll
    for (int mt = 0; mt < 4; mt++)
#pragma unroll
        for (int nt = 0; nt < 8; nt++) {
            int gcol = warpN * 64 + nt * 8 + 2 * t;
            float bb0 = bias[gcol], bb1 = bias[gcol + 1];
            acc[mt][nt][0] += bb0; acc[mt][nt][1] += bb1;
            acc[mt][nt][2] += bb0; acc[mt][nt][3] += bb1;
            if (ACT) {
#pragma unroll
                for (int q = 0; q < 4; q++) acc[mt][nt][q] = fmaxf(acc[mt][nt][q], 0.f);
            }
        }

    if (SOFTMAX) {
        float rmax[4][2], rsum[4][2];
#pragma unroll
        for (int mt = 0; mt < 4; mt++)
#pragma unroll
            for (int h = 0; h < 2; h++) {
                float m = -1e30f;
#pragma unroll
                for (int nt = 0; nt < 8; nt++)
                    m = fmaxf(m, fmaxf(acc[mt][nt][2 * h], acc[mt][nt][2 * h + 1]));
                m = fmaxf(m, __shfl_xor_sync(0xffffffffu, m, 1));
                m = fmaxf(m, __shfl_xor_sync(0xffffffffu, m, 2));
                rmax[mt][h] = m;
            }
        if (t == 0)
#pragma unroll
            for (int mt = 0; mt < 4; mt++)
#pragma unroll
                for (int h = 0; h < 2; h++)
                    red[warpM * 64 + mt * 16 + g + h * 8][warpN] = rmax[mt][h];
        __syncthreads();
#pragma unroll
        for (int mt = 0; mt < 4; mt++)
#pragma unroll
            for (int h = 0; h < 2; h++) {
                int r = warpM * 64 + mt * 16 + g + h * 8;
                rmax[mt][h] = fmaxf(fmaxf(red[r][0], red[r][1]),
                                    fmaxf(red[r][2], red[r][3]));
            }
        __syncthreads();
#pragma unroll
        for (int mt = 0; mt < 4; mt++)
#pragma unroll
            for (int h = 0; h < 2; h++) {
                float s = 0.f;
#pragma unroll
                for (int nt = 0; nt < 8; nt++) {
                    float e0 = __expf(acc[mt][nt][2 * h]     - rmax[mt][h]);
                    float e1 = __expf(acc[mt][nt][2 * h + 1] - rmax[mt][h]);
                    acc[mt][nt][2 * h] = e0; acc[mt][nt][2 * h + 1] = e1;
                    s += e0 + e1;
                }
                s += __shfl_xor_sync(0xffffffffu, s, 1);
                s += __shfl_xor_sync(0xffffffffu, s, 2);
                rsum[mt][h] = s;
            }
        if (t == 0)
#pragma unroll
            for (int mt = 0; mt < 4; mt++)
#pragma unroll
                for (int h = 0; h < 2; h++)
                    red[warpM * 64 + mt * 16 + g + h * 8][warpN] = rsum[mt][h];
        __syncthreads();
#pragma unroll
        for (int mt = 0; mt < 4; mt++)
#pragma unroll
            for (int h = 0; h < 2; h++) {
                int r = warpM * 64 + mt * 16 + g + h * 8;
                float s = red[r][0] + red[r][1] + red[r][2] + red[r][3];
                float inv = 1.f / s;
#pragma unroll
                for (int nt = 0; nt < 8; nt++) {
                    acc[mt][nt][2 * h]     *= inv;
                    acc[mt][nt][2 * h + 1] *= inv;
                }
            }
    }

#pragma unroll
    for (int mt = 0; mt < 4; mt++) {
        int gm = m0 + warpM * 64 + mt * 16 + g;
#pragma unroll
        for (int nt = 0; nt < 8; nt++) {
            int gcol = warpN * 64 + nt * 8 + 2 * t;
            float v00 = acc[mt][nt][0], v01 = acc[mt][nt][1];
            float v10 = acc[mt][nt][2], v11 = acc[mt][nt][3];
            if (OUTMODE == 0) {
                if (gm < Mrows)
                    *reinterpret_cast<float2*>(&C[cb + (long)gm * NREAL + gcol]) = make_float2(v00, v01);
                if (gm + 8 < Mrows)
                    *reinterpret_cast<float2*>(&C[cb + (long)(gm + 8) * NREAL + gcol]) = make_float2(v10, v11);
            } else {
                if (gm < Mrows) {
                    __nv_bfloat162 h(__float2bfloat16(v00), __float2bfloat16(v01));
                    __nv_bfloat162 l(__float2bfloat16(v00 - __bfloat162float(h.x)),
                                     __float2bfloat16(v01 - __bfloat162float(h.y)));
                    *reinterpret_cast<__nv_bfloat162*>(&Chi[cb + (long)gm * NREAL + gcol]) = h;
                    *reinterpret_cast<__nv_bfloat162*>(&Clo[cb + (long)gm * NREAL + gcol]) = l;
                }
                if (gm + 8 < Mrows) {
                    __nv_bfloat162 h(__float2bfloat16(v10), __float2bfloat16(v11));
                    __nv_bfloat162 l(__float2bfloat16(v10 - __bfloat162float(h.x)),
                                     __float2bfloat16(v11 - __bfloat162float(h.y)));
                    *reinterpret_cast<__nv_bfloat162*>(&Chi[cb + (long)(gm + 8) * NREAL + gcol]) = h;
                    *reinterpret_cast<__nv_bfloat162*>(&Clo[cb + (long)(gm + 8) * NREAL + gcol]) = l;
                }
            }
        }
    }
}

// ============================================================================
// gated0 GEMM (BM=128, BN=64, Nreal=48) with FUSED sigmoid*tanh + 1x1 scale
// epilogue -> writes hA [.,24] directly. 256 threads, 8 warps as 4(M)x2(N).
// ============================================================================
__global__ __launch_bounds__(256) void gemm_gated0(
    const __nv_bfloat16* __restrict__ Ahi, const __nv_bfloat16* __restrict__ Alo,
    const uint32* __restrict__ Bhi, const uint32* __restrict__ Blo,
    const float* __restrict__ gb0, const float* __restrict__ fb0,
    const float* __restrict__ sW, const float* __restrict__ sB,
    float* __restrict__ hOut, int Mrows, long sA)
{
    constexpr int NREAL = 48;
    constexpr int NT   = 4;
    constexpr int BSTR = 72;
    constexpr int ASZ  = 128 * 20;
    constexpr int BSZ  = 16 * BSTR;
    constexpr int K    = 512;
    constexpr int LDA  = 256;
    extern __shared__ __align__(16) uint32 sm[];
    __shared__ float zs[128][49];
    __shared__ float zz[128][25];
    __shared__ float sws[24][24];
    __shared__ float sbs[24];

    const int tid   = threadIdx.x;
    const int wid   = tid >> 5, lane = tid & 31;
    const int warpM = wid >> 1, warpN = wid & 1;
    const int g     = lane >> 2, t = lane & 3;
    const int m0    = blockIdx.x * 128;
    const __nv_bfloat16* Ah = Ahi + (long)blockIdx.z * sA;
    const __nv_bfloat16* Al = Alo + (long)blockIdx.z * sA;

    for (int i = tid; i < 576; i += 256) sws[i / 24][i % 24] = sW[i];
    if (tid < 24) sbs[tid] = sB[tid];

    uint32 smbase;
    asm("{ .reg .u64 tmp; cvta.to.shared.u64 tmp, %1; cvt.u32.u64 %0, tmp; }"
        : "=r"(smbase) : "l"(sm));

    float acc[2][NT][4];
#pragma unroll
    for (int i = 0; i < 2; i++)
#pragma unroll
        for (int j = 0; j < NT; j++)
#pragma unroll
            for (int k = 0; k < 4; k++) acc[i][j][k] = 0.f;

    const int nk = K / 32;

    auto fill = [&](int kt) {
        const int st = kt & 1;
        const int k0 = kt * 32;
#pragma unroll
        for (int m = 0; m < 2; m++) {
            const __nv_bfloat16* Asrc = m ? Al : Ah;
#pragma unroll
            for (int j = 0; j < 2; j++) {
                int c = tid + j * 256;
                int r = c >> 2, q = c & 3;
                int gm = m0 + r;
                uint32 d = smbase + ((st * 2 + m) * ASZ + r * 20 + q * 4) * 4;
                cp16(d, Asrc + (long)gm * LDA + k0 + q * 8, gm < Mrows);
            }
        }
#pragma unroll
        for (int m = 0; m < 2; m++) {
            const uint32* Bsrc = m ? Blo : Bhi;
            int c = tid;             // 16 p-rows x 16 chunks = 256
            int p = c >> 4, q = c & 15;
            int gn = q * 4;
            uint32 d = smbase + (4 * ASZ + (st * 2 + m) * BSZ + p * BSTR + q * 4) * 4;
            cp16(d, Bsrc + (long)(k0 / 2 + p) * NREAL + gn, gn < NREAL);
        }
        cpcommit();
    };

    fill(0);
    for (int kt = 0; kt < nk; kt++) {
        if (kt + 1 < nk) { fill(kt + 1); cpwait<1>(); } else { cpwait<0>(); }
        __syncthreads();
        const int st = kt & 1;
        const uint32* A_h = sm + (st * 2 + 0) * ASZ;
        const uint32* A_l = sm + (st * 2 + 1) * ASZ;
        const uint32* B_h = sm + 4 * ASZ + (st * 2 + 0) * BSZ;
        const uint32* B_l = sm + 4 * ASZ + (st * 2 + 1) * BSZ;
#pragma unroll
        for (int ks = 0; ks < 2; ks++) {
            uint32 ah[2][4], al[2][4];
            const int w0 = ks * 8 + t;
#pragma unroll
            for (int mt = 0; mt < 2; mt++) {
                int rr = warpM * 32 + mt * 16 + g;
                ah[mt][0] = A_h[rr * 20 + w0];       ah[mt][1] = A_h[(rr + 8) * 20 + w0];
                ah[mt][2] = A_h[rr * 20 + w0 + 4];   ah[mt][3] = A_h[(rr + 8) * 20 + w0 + 4];
                al[mt][0] = A_l[rr * 20 + w0];       al[mt][1] = A_l[(rr + 8) * 20 + w0];
                al[mt][2] = A_l[rr * 20 + w0 + 4];   al[mt][3] = A_l[(rr + 8) * 20 + w0 + 4];
            }
#pragma unroll
            for (int nt = 0; nt < NT; nt++) {
                int nn = warpN * (NT * 8) + nt * 8 + g;
                uint32 bh0 = B_h[w0 * BSTR + nn], bh1 = B_h[(w0 + 4) * BSTR + nn];
                uint32 bl0 = B_l[w0 * BSTR + nn], bl1 = B_l[(w0 + 4) * BSTR + nn];
#pragma unroll
                for (int mt = 0; mt < 2; mt++) {
                    mma_bf16(acc[mt][nt], ah[mt], bh0, bh1);
                    mma_bf16(acc[mt][nt], ah[mt], bl0, bl1);
                    mma_bf16(acc[mt][nt], al[mt], bh0, bh1);
                }
            }
        }
        __syncthreads();
    }

    // ---- fused epilogue: bias -> zs, sig*tanh -> zz, 1x1 -> hOut ----
#pragma unroll
    for (int mt = 0; mt < 2; mt++) {
        int r0 = warpM * 32 + mt * 16 + g;
#pragma unroll
        for (int nt = 0; nt < NT; nt++) {
            int col = warpN * (NT * 8) + nt * 8 + 2 * t;
            if (col < NREAL) {
                float b0 = (col < 24)     ? gb0[col]     : fb0[col - 24];
                float b1 = (col + 1 < 24) ? gb0[col + 1] : fb0[col + 1 - 24];
                zs[r0][col]     = acc[mt][nt][0] + b0;
                zs[r0][col + 1] = acc[mt][nt][1] + b1;
                zs[r0 + 8][col]     = acc[mt][nt][2] + b0;
                zs[r0 + 8][col + 1] = acc[mt][nt][3] + b1;
            }
        }
    }
    __syncthreads();
    if (tid < 128) {
#pragma unroll
        for (int c = 0; c < 24; c++)
            zz[tid][c] = sigmoidf_(zs[tid][c]) * tanhf_(zs[tid][24 + c]);
    }
    __syncthreads();
    {
        int r = tid & 127, half = tid >> 7;
        long gm = m0 + r;
        if (gm < Mrows) {
            float o[12];
#pragma unroll
            for (int j = 0; j < 12; j++) o[j] = sbs[half * 12 + j];
#pragma unroll
            for (int c = 0; c < 24; c++) {
                float zv = zz[r][c];
#pragma unroll
                for (int j = 0; j < 12; j++) o[j] += zv * sws[c][half * 12 + j];
            }
            float* ob = hOut + ((long)blockIdx.z * Mrows + gm) * 24 + half * 12;
#pragma unroll
            for (int j = 0; j < 6; j++)
                *reinterpret_cast<float2*>(&ob[2 * j]) = make_float2(o[2 * j], o[2 * j + 1]);
        }
    }
}

// ============================================================================
// fp32 -> hi/lo bf16 split (element arrays, n % 4 == 0)
// ============================================================================
__global__ void split_bf16_vec(const float* __restrict__ s,
                               __nv_bfloat16* __restrict__ hi,
                               __nv_bfloat16* __restrict__ lo, long n)
{
    long i = ((long)blockIdx.x * 256 + threadIdx.x) * 4;
    if (i >= n) return;
    float4 v = *reinterpret_cast<const float4*>(s + i);
    __nv_bfloat16 h0 = __float2bfloat16(v.x), h1 = __float2bfloat16(v.y);
    __nv_bfloat16 h2 = __float2bfloat16(v.z), h3 = __float2bfloat16(v.w);
    __nv_bfloat16 l0 = __float2bfloat16(v.x - __bfloat162float(h0));
    __nv_bfloat16 l1 = __float2bfloat16(v.y - __bfloat162float(h1));
    __nv_bfloat16 l2 = __float2bfloat16(v.z - __bfloat162float(h2));
    __nv_bfloat16 l3 = __float2bfloat16(v.w - __bfloat162float(h3));
    reinterpret_cast<__nv_bfloat162*>(hi + i)[0] = __nv_bfloat162(h0, h1);
    reinterpret_cast<__nv_bfloat162*>(hi + i)[1] = __nv_bfloat162(h2, h3);
    reinterpret_cast<__nv_bfloat162*>(lo + i)[0] = __nv_bfloat162(l0, l1);
    reinterpret_cast<__nv_bfloat162*>(lo + i)[1] = __nv_bfloat162(l2, l3);
}

// ============================================================================
// fp32 weight [K][N] -> hi/lo k-paired words [K/2][N]
// ============================================================================
__global__ void split_pairB(const float* __restrict__ W, uint32* __restrict__ bhi,
                            uint32* __restrict__ blo, int K2, int N)
{
    int idx = blockIdx.x * 256 + threadIdx.x;
    if (idx >= K2 * N) return;
    int p = idx / N, n = idx % N;
    float w0 = W[(long)(2 * p) * N + n];
    float w1 = W[(long)(2 * p + 1) * N + n];
    __nv_bfloat16 h0 = __float2bfloat16(w0), h1 = __float2bfloat16(w1);
    __nv_bfloat16 l0 = __float2bfloat16(w0 - __bfloat162float(h0));
    __nv_bfloat16 l1 = __float2bfloat16(w1 - __bfloat162float(h1));
    __nv_bfloat162 hw(h0, h1), lw(l0, l1);
    bhi[idx] = *reinterpret_cast<uint32*>(&hw);
    blo[idx] = *reinterpret_cast<uint32*>(&lw);
}

// ============================================================================
// gated0 weights: pack gW0|fW0 -> k-paired hi/lo words [256][48] directly.
// ============================================================================
__global__ void pack_split_g0(const float* __restrict__ gW, const float* __restrict__ fW,
                              uint32* __restrict__ bhi, uint32* __restrict__ blo)
{
    int idx = blockIdx.x * 256 + threadIdx.x;
    if (idx >= 256 * 48) return;
    int p = idx / 48, n = idx % 48;
    const float* src = (n < 24) ? gW : fW;
    int nn = (n < 24) ? n : n - 24;
    float w0 = src[(2 * p) * 24 + nn];
    float w1 = src[(2 * p + 1) * 24 + nn];
    __nv_bfloat16 h0 = __float2bfloat16(w0), h1 = __float2bfloat16(w1);
    __nv_bfloat16 l0 = __float2bfloat16(w0 - __bfloat162float(h0));
    __nv_bfloat16 l1 = __float2bfloat16(w1 - __bfloat162float(h1));
    __nv_bfloat162 hw(h0, h1), lw(l0, l1);
    bhi[idx] = *reinterpret_cast<uint32*>(&hw);
    blo[idx] = *reinterpret_cast<uint32*>(&lw);
}

// ============================================================================
// Fused dilated gated layer (24 ch, f32x2); one 128-tile per CTA.
// ============================================================================
__global__ __launch_bounds__(128) void dilated_gated(
    const float* __restrict__ hin, float* __restrict__ hout,
    const float* __restrict__ gateW, const float* __restrict__ gateB,
    const float* __restrict__ filtW, const float* __restrict__ filtB,
    const float* __restrict__ scaleW, const float* __restrict__ scaleB,
    int layer, int Tin, int Tout, int d)
{
    __shared__ float xs0[128][25];
    __shared__ float xs1[128][25];
    __shared__ ULL gp0[24][12], gp1[24][12], fp0[24][12], fp1[24][12], sp[24][12];
    __shared__ ULL gb2[12], fb2[12], sb2[12];
    const int tid = threadIdx.x;
    const int b   = blockIdx.y;
    const int t0  = blockIdx.x * 128;
    const int wbase = layer * 1152;
    for (int i = tid; i < 288; i += 128) {
        int c = i / 12, p = i % 12, o = 2 * p;
        gp0[c][p] = pk2(gateW[wbase + c * 24 + o],       gateW[wbase + c * 24 + o + 1]);
        gp1[c][p] = pk2(gateW[wbase + 576 + c * 24 + o], gateW[wbase + 576 + c * 24 + o + 1]);
        fp0[c][p] = pk2(filtW[wbase + c * 24 + o],       filtW[wbase + c * 24 + o + 1]);
        fp1[c][p] = pk2(filtW[wbase + 576 + c * 24 + o], filtW[wbase + 576 + c * 24 + o + 1]);
        sp[c][p]  = pk2(scaleW[layer * 576 + c * 24 + o], scaleW[layer * 576 + c * 24 + o + 1]);
    }
    if (tid < 12) {
        gb2[tid] = pk2(gateB[layer * 24 + 2 * tid], gateB[layer * 24 + 2 * tid + 1]);
        fb2[tid] = pk2(filtB[layer * 24 + 2 * tid], filtB[layer * 24 + 2 * tid + 1]);
        sb2[tid] = pk2(scaleB[layer * 24 + 2 * tid], scaleB[layer * 24 + 2 * tid + 1]);
    }
    const float* hb = hin + (long)b * Tin * 24;
    for (int i = tid; i < 128 * 24; i += 128) {
        int r = i / 24, c = i % 24;
        int ta = t0 + r, tc = t0 + d + r;
        xs0[r][c] = (ta < Tin) ? hb[(long)ta * 24 + c] : 0.f;
        xs1[r][c] = (tc < Tin) ? hb[(long)tc * 24 + c] : 0.f;
    }
    __syncthreads();
    int t = t0 + tid;
    if (t >= Tout) return;
    ULL gA2[12], fA2[12];
#pragma unroll
    for (int p = 0; p < 12; p++) { gA2[p] = gb2[p]; fA2[p] = fb2[p]; }
#pragma unroll
    for (int c = 0; c < 24; c++) {
        ULL x0d = dup2(xs0[tid][c]);
        ULL x1d = dup2(xs1[tid][c]);
#pragma unroll
        for (int p = 0; p < 12; p++) {
            ffma2(gA2[p], x0d, gp0[c][p]);
            ffma2(gA2[p], x1d, gp1[c][p]);
            ffma2(fA2[p], x0d, fp0[c][p]);
            ffma2(fA2[p], x1d, fp1[c][p]);
        }
    }
    float z[24];
#pragma unroll
    for (int p = 0; p < 12; p++) {
        float2 gv = unpk2(gA2[p]);
        float2 fv = unpk2(fA2[p]);
        z[2 * p]     = sigmoidf_(gv.x) * tanhf_(fv.x);
        z[2 * p + 1] = sigmoidf_(gv.y) * tanhf_(fv.y);
    }
    ULL o2[12];
#pragma unroll
    for (int p = 0; p < 12; p++) o2[p] = sb2[p];
#pragma unroll
    for (int c = 0; c < 24; c++) {
        ULL zd = dup2(z[c]);
#pragma unroll
        for (int p = 0; p < 12; p++) ffma2(o2[p], zd, sp[c][p]);
    }
    ULL* ob = reinterpret_cast<ULL*>(hout + ((long)b * Tout + t) * 24);
#pragma unroll
    for (int p = 0; p < 12; p++) ob[p] = o2[p];
}

// ============================================================================
// Final residual add + res conv (24->128) + relu -> a0 as bf16 hi/lo split
// ============================================================================
__global__ __launch_bounds__(128) void resconv_relu(
    const float* __restrict__ prev8, const float* __restrict__ out8,
    const float* __restrict__ resW, const float* __restrict__ resB,
    __nv_bfloat16* __restrict__ a0hi, __nv_bfloat16* __restrict__ a0lo)
{
    __shared__ float ss[32][25];
    __shared__ float Ws[24][128];
    __shared__ float bs[128];
    const int tid = threadIdx.x;
    const int b   = blockIdx.y;
    const int t0  = blockIdx.x * 32;
    for (int i = tid; i < 24 * 128; i += 128) Ws[i / 128][i % 128] = resW[8 * 24 * 128 + i];
    bs[tid] = resB[8 * 128 + tid];
    const float* pb = prev8 + ((long)b * 15872 + 256) * 24;
    const float* ob = out8  + (long)b * TFIN * 24;
    for (int i = tid; i < 32 * 24; i += 128) {
        int r = i / 24, c = i % 24;
        long t = t0 + r;
        ss[r][c] = pb[t * 24 + c] + ob[t * 24 + c];
    }
    __syncthreads();
    long obase = ((long)b * TFIN + t0) * 128;
#pragma unroll 4
    for (int r = 0; r < 32; r++) {
        float a = bs[tid];
#pragma unroll
        for (int c = 0; c < 24; c++) a += ss[r][c] * Ws[c][tid];
        a = fmaxf(a, 0.f);
        __nv_bfloat16 h = __float2bfloat16(a);
        __nv_bfloat16 l = __float2bfloat16(a - __bfloat162float(h));
        a0hi[obase + (long)r * 128 + tid] = h;
        a0lo[obase + (long)r * 128 + tid] = l;
    }
}

// ============================================================================
extern "C" void kernel_launch(void* const* d_in, const int* in_sizes, int n_in,
                              void* d_out, int out_size)
{
    const float* x        = (const float*)d_in[0];
    const float* causal_W = (const float*)d_in[1];
    const float* causal_b = (const float*)d_in[2];
    const float* gW0      = (const float*)d_in[3];
    const float* gb0      = (const float*)d_in[4];
    const float* fW0      = (const float*)d_in[5];
    const float* fb0      = (const float*)d_in[6];
    const float* sW0      = (const float*)d_in[7];
    const float* sb0      = (const float*)d_in[8];
    const float* gateW    = (const float*)d_in[9];
    const float* gateB    = (const float*)d_in[10];
    const float* filtW    = (const float*)d_in[11];
    const float* filtB    = (const float*)d_in[12];
    const float* scaleW   = (const float*)d_in[13];
    const float* scaleB   = (const float*)d_in[14];
    const float* resW     = (const float*)d_in[15];
    const float* resB     = (const float*)d_in[16];
    const float* f1W      = (const float*)d_in[17];
    const float* f1b      = (const float*)d_in[18];
    const float* f2W      = (const float*)d_in[19];
    const float* f2b      = (const float*)d_in[20];
    float* out = (float*)d_out;

    __nv_bfloat16 *xhi, *xlo, *y1hi, *y1lo, *a0hi, *a0lo, *a1hi, *a1lo;
    float *hA, *hB;
    uint32 *WcauHi, *WcauLo, *Wg0Hi, *Wg0Lo, *Wf1Hi, *Wf1Lo, *Wf2Hi, *Wf2Lo;
    cudaGetSymbolAddress((void**)&xhi,  g_xhi);  cudaGetSymbolAddress((void**)&xlo,  g_xlo);
    cudaGetSymbolAddress((void**)&y1hi, g_y1hi); cudaGetSymbolAddress((void**)&y1lo, g_y1lo);
    cudaGetSymbolAddress((void**)&hA,   g_hA);   cudaGetSymbolAddress((void**)&hB,   g_hB);
    cudaGetSymbolAddress((void**)&a0hi, g_a0hi); cudaGetSymbolAddress((void**)&a0lo, g_a0lo);
    cudaGetSymbolAddress((void**)&a1hi, g_a1hi); cudaGetSymbolAddress((void**)&a1lo, g_a1lo);
    cudaGetSymbolAddress((void**)&WcauHi, g_WcauHi); cudaGetSymbolAddress((void**)&WcauLo, g_WcauLo);
    cudaGetSymbolAddress((void**)&Wg0Hi,  g_Wg0Hi);  cudaGetSymbolAddress((void**)&Wg0Lo,  g_Wg0Lo);
    cudaGetSymbolAddress((void**)&Wf1Hi,  g_Wf1Hi);  cudaGetSymbolAddress((void**)&Wf1Lo,  g_Wf1Lo);
    cudaGetSymbolAddress((void**)&Wf2Hi,  g_Wf2Hi);  cudaGetSymbolAddress((void**)&Wf2Lo,  g_Wf2Lo);

    const int SMEM_N256 = (6 * 2560 + 6 * 16 * 264) * 4;    // 162816 B
    const int SMEM64    = (4 * 128 * 20 + 4 * 16 * 72) * 4; // 59392 B
    cudaFuncSetAttribute((const void*)gemm_n256<1,0,0>, cudaFuncAttributeMaxDynamicSharedMemorySize, SMEM_N256);
    cudaFuncSetAttribute((const void*)gemm_n256<1,1,0>, cudaFuncAttributeMaxDynamicSharedMemorySize, SMEM_N256);
    cudaFuncSetAttribute((const void*)gemm_n256<0,0,1>, cudaFuncAttributeMaxDynamicSharedMemorySize, SMEM_N256);
    cudaFuncSetAttribute((const void*)gemm_gated0,      cudaFuncAttributeMaxDynamicSharedMemorySize, SMEM64);

    // 0. preprocessing (ordered so the 6th launch = causal GEMM for ncu -s 5)
    long nx = (long)B_ * T0_ * 256;
    split_bf16_vec<<<(int)(nx / 4 / 256), 256>>>(x, xhi, xlo, nx);                       // 1
    split_pairB<<<(256 * 256 + 255) / 256, 256>>>(causal_W, WcauHi, WcauLo, 256, 256);   // 2
    split_pairB<<<(64 * 256 + 255) / 256, 256>>>(f1W, Wf1Hi, Wf1Lo, 64, 256);            // 3
    split_pairB<<<(128 * 256 + 255) / 256, 256>>>(f2W, Wf2Hi, Wf2Lo, 128, 256);          // 4
    pack_split_g0<<<48, 256>>>(gW0, fW0, Wg0Hi, Wg0Lo);                                  // 5

    // 1. causal conv as split-bf16 GEMM (K=512 overlap trick), out y1 hi/lo  // 6
    gemm_n256<1,0,0><<<dim3(129, 1, B_), 256, SMEM_N256>>>(
        xhi, xlo, WcauHi, WcauLo, causal_b, nullptr, y1hi, y1lo,
        T1_, 512, 256, (long)T0_ * 256, (long)T1_ * 256);

    // 2. gated0 GEMM + fused activation + 1x1 -> hA
    gemm_gated0<<<dim3(128, 1, B_), 256, SMEM64>>>(
        y1hi, y1lo, Wg0Hi, Wg0Lo, gb0, fb0, sW0, sb0, hA,
        T2_, (long)T1_ * 256);

    // 3. nine dilated gated layers (ping-pong hA/hB)
    int Tin = T2_;
    float* hin  = hA;
    float* hnew = hB;
    for (int i = 0; i < 9; i++) {
        int d = 2 << i;
        int Tout = Tin - d;
        dim3 g((Tout + 127) / 128, B_);
        dilated_gated<<<g, 128>>>(hin, hnew, gateW, gateB, filtW, filtB,
                                  scaleW, scaleB, i, Tin, Tout, d);
        float* tmp = hin; hin = hnew; hnew = tmp;
        Tin = Tout;
    }
    // hin = layer-8 output (T=15360), hnew = layer-7 output (T=15872)

    // 4. residual add + res conv (only res_W[8] matters) + relu -> a0 hi/lo
    resconv_relu<<<dim3(480, B_), 128>>>(hnew, hin, resW, resB, a0hi, a0lo);

    // 5. f1 + relu -> a1 hi/lo
    gemm_n256<1,1,0><<<dim3(960, 1, 1), 256, SMEM_N256>>>(
        a0hi, a0lo, Wf1Hi, Wf1Lo, f1b, nullptr, a1hi, a1lo,
        B_ * TFIN, 128, 128, 0, 0);

    // 6. f2 + fused exact softmax -> probabilities fp32 in d_out
    gemm_n256<0,0,1><<<dim3(960, 1, 1), 256, SMEM_N256>>>(
        a1hi, a1lo, Wf2Hi, Wf2Lo, f2b, out, nullptr, nullptr,
        B_ * TFIN, 256, 256, 0, 0);
}